// round 1
// baseline (speedup 1.0000x reference)
#include <cuda_runtime.h>
#include <math.h>

// ---------------------------------------------------------------------------
// Problem constants
// ---------------------------------------------------------------------------
#define HH 64
#define WW 64
#define HWSZ 4096
#define CIN 128
#define TT 4
#define DM 256
#define NQ 300
#define NP 8
#define NLAY 6
#define BATCH 2
#define MROWS (BATCH*HWSZ)      // 8192 spatial rows
#define MQ (BATCH*NQ)           // 600 query rows
#define MS (MQ*NP)              // 4800 sample rows
#define KP1 2304                // 3*3*256

// ---------------------------------------------------------------------------
// Scratch (single static device buffer, offsets in floats)
// ---------------------------------------------------------------------------
constexpr size_t O_WCOMB = 0;                        // 256*512
constexpr size_t O_BCOMB = O_WCOMB + 256*512;        // 256
constexpr size_t O_PY    = O_BCOMB + 256;            // 64*128
constexpr size_t O_PX    = O_PY + 64*128;            // 64*128
constexpr size_t O_X     = O_PX + 64*128;            // 8192*256
constexpr size_t O_LAT   = O_X + (size_t)MROWS*DM;   // 8192*256
constexpr size_t O_COL   = O_LAT + (size_t)MROWS*DM; // 8192*2304
constexpr size_t O_F0    = O_COL + (size_t)MROWS*KP1;// 8192*256
constexpr size_t O_Q     = O_F0 + (size_t)MROWS*DM;  // 600*256
constexpr size_t O_H1    = O_Q + MQ*DM;
constexpr size_t O_REF   = O_H1 + MQ*DM;             // 600*8*2
constexpr size_t O_FLAT  = O_REF + MQ*NP*2;          // 4800*2304
constexpr size_t O_PV    = O_FLAT + (size_t)MS*KP1;  // 4800*256
constexpr size_t O_KVP   = O_PV + (size_t)MS*DM;
constexpr size_t O_KV    = O_KVP + MQ*DM;
constexpr size_t O_QP    = O_KV + MQ*DM;
constexpr size_t O_KVT   = O_QP + MQ*DM;             // 2*256*300
constexpr size_t O_S     = O_KVT + MQ*DM;            // 2*300*300
constexpr size_t O_AO    = O_S + BATCH*NQ*NQ;
constexpr size_t O_HB    = O_AO + MQ*DM;
constexpr size_t O_BOX   = O_HB + MQ*DM;             // 600*4
constexpr size_t G_TOTAL = O_BOX + MQ*4;

__device__ float g_buf[G_TOTAL];

// ---------------------------------------------------------------------------
// Stem weight combine: Wcomb[d][i*4+t] = 0.25 * sum_c w_in[d][c]*weff[c][i][t]
// weff from conv3d(kernel 3, pad 1) followed by mean over T=4.
// ---------------------------------------------------------------------------
__global__ __launch_bounds__(256)
void k_wcomb(const float* __restrict__ w_tf, const float* __restrict__ w_in,
             const float* __restrict__ b_tf, const float* __restrict__ b_in,
             float* __restrict__ wcomb, float* __restrict__ bcomb) {
  int idx = blockIdx.x * 256 + threadIdx.x;
  if (idx < 256 * 512) {
    int dm = idx >> 9, k = idx & 511, i = k >> 2, t = k & 3;
    float s = 0.f;
    for (int c = 0; c < CIN; ++c) {
      const float* wt = w_tf + (c * CIN + i) * 3;
      float we = wt[1];
      if (t != 3) we += wt[0];
      if (t != 0) we += wt[2];
      s += w_in[dm * CIN + c] * we;
    }
    wcomb[idx] = 0.25f * s;
  }
  if (idx < 256) {
    float s = b_in[idx];
    for (int c = 0; c < CIN; ++c) s += w_in[idx * CIN + c] * b_tf[c];
    bcomb[idx] = s;
  }
}

// sine positional tables: py[h][c] (c<128), px[w][c]
__global__ __launch_bounds__(256)
void k_pos(float* __restrict__ py, float* __restrict__ px) {
  int idx = blockIdx.x * 256 + threadIdx.x;
  if (idx >= 2 * 64 * 128) return;
  int half = idx / (64 * 128);
  int r = idx - half * (64 * 128);
  int hw = r >> 7, c = r & 127;
  float dim_t = powf(10000.f, 2.f * (float)(c >> 2) / 64.f);
  float v = (float)(hw + 1) / (64.f + 1e-6f) * 2.f * 3.14159265358979323846f;
  float a = v / dim_t;
  float o = (c & 1) ? cosf(a) : sinf(a);
  if (half) px[r] = o; else py[r] = o;
}

// ---------------------------------------------------------------------------
// Generic SGEMM: C[M,N] = A[M,K] (row-major) @ Bw[N,K]^T (row-major weights)
// EPI: 0 = +bias, 1 = +bias,relu, 2 = +bias +res (residual add)
// ---------------------------------------------------------------------------
template<int EPI>
__global__ __launch_bounds__(256)
void sgemm_nt(const float* __restrict__ A, const float* __restrict__ Bw,
              const float* __restrict__ bias, const float* __restrict__ res,
              float* __restrict__ C, int M, int N, int K) {
  const int BM = 128, BN = 64, BK = 16;
  __shared__ float As[BK][BM + 4];
  __shared__ float Bs[BK][BN + 4];
  int bm = blockIdx.y * BM, bn = blockIdx.x * BN;
  int tid = threadIdx.x;
  int tx = tid & 15, ty = tid >> 4;
  float acc[8][4] = {};
  for (int k0 = 0; k0 < K; k0 += BK) {
    // A tile: 128x16 = 512 float4, 2 per thread
    #pragma unroll
    for (int l = 0; l < 2; ++l) {
      int li = tid + l * 256;
      int m = li >> 2;
      int kq = (li & 3) * 4;
      int gm = bm + m, gk = k0 + kq;
      float4 v = make_float4(0.f, 0.f, 0.f, 0.f);
      if (gm < M && gk < K)
        v = *reinterpret_cast<const float4*>(A + (size_t)gm * K + gk);
      As[kq + 0][m] = v.x; As[kq + 1][m] = v.y;
      As[kq + 2][m] = v.z; As[kq + 3][m] = v.w;
    }
    // B tile: 64x16 = 256 float4, 1 per thread
    {
      int m = tid >> 2;
      int kq = (tid & 3) * 4;
      int gn = bn + m, gk = k0 + kq;
      float4 v = make_float4(0.f, 0.f, 0.f, 0.f);
      if (gn < N && gk < K)
        v = *reinterpret_cast<const float4*>(Bw + (size_t)gn * K + gk);
      Bs[kq + 0][m] = v.x; Bs[kq + 1][m] = v.y;
      Bs[kq + 2][m] = v.z; Bs[kq + 3][m] = v.w;
    }
    __syncthreads();
    #pragma unroll
    for (int kk = 0; kk < BK; ++kk) {
      float4 a0 = *reinterpret_cast<const float4*>(&As[kk][ty * 8]);
      float4 a1 = *reinterpret_cast<const float4*>(&As[kk][ty * 8 + 4]);
      float4 b0 = *reinterpret_cast<const float4*>(&Bs[kk][tx * 4]);
      float a[8] = {a0.x, a0.y, a0.z, a0.w, a1.x, a1.y, a1.z, a1.w};
      float b[4] = {b0.x, b0.y, b0.z, b0.w};
      #pragma unroll
      for (int i = 0; i < 8; ++i)
        #pragma unroll
        for (int j = 0; j < 4; ++j) acc[i][j] += a[i] * b[j];
    }
    __syncthreads();
  }
  #pragma unroll
  for (int i = 0; i < 8; ++i) {
    int gm = bm + ty * 8 + i;
    if (gm >= M) continue;
    #pragma unroll
    for (int j = 0; j < 4; ++j) {
      int gn = bn + tx * 4 + j;
      if (gn >= N) continue;
      float v = acc[i][j] + (bias ? bias[gn] : 0.f);
      if (EPI == 1) v = fmaxf(v, 0.f);
      if (EPI == 2) v += res[(size_t)gm * N + gn];
      C[(size_t)gm * N + gn] = v;
    }
  }
}

// ---------------------------------------------------------------------------
// Stem GEMM: A gathered from feat[b,t,i,h,w] with k=i*4+t, epilogue adds pos.
// M=8192 (b*4096+hw), N=256, K=512. Output channel-last (b,hw,c).
// ---------------------------------------------------------------------------
__global__ __launch_bounds__(256)
void k_stem(const float* __restrict__ feat, const float* __restrict__ wcomb,
            const float* __restrict__ bcomb, const float* __restrict__ py,
            const float* __restrict__ px, float* __restrict__ C) {
  const int BM = 128, BN = 64, BK = 16, K = 512, N = 256;
  __shared__ float As[BK][BM + 4];
  __shared__ float Bs[BK][BN + 4];
  int bm = blockIdx.y * BM, bn = blockIdx.x * BN;
  int tid = threadIdx.x;
  int tx = tid & 15, ty = tid >> 4;
  float acc[8][4] = {};
  for (int k0 = 0; k0 < K; k0 += BK) {
    // A: 2048 scalars, coalesced over hw
    #pragma unroll
    for (int l = 0; l < 8; ++l) {
      int e = tid + l * 256;
      int k = e >> 7, mm = e & 127;
      int gm = bm + mm, gk = k0 + k;
      int b = gm >> 12, hw = gm & 4095;
      int i = gk >> 2, t = gk & 3;
      As[k][mm] = feat[(size_t)(((b << 2) + t) * CIN + i) * HWSZ + hw];
    }
    {
      int m = tid >> 2, kq = (tid & 3) * 4;
      float4 v = *reinterpret_cast<const float4*>(wcomb + (size_t)(bn + m) * K + k0 + kq);
      Bs[kq + 0][m] = v.x; Bs[kq + 1][m] = v.y;
      Bs[kq + 2][m] = v.z; Bs[kq + 3][m] = v.w;
    }
    __syncthreads();
    #pragma unroll
    for (int kk = 0; kk < BK; ++kk) {
      float4 a0 = *reinterpret_cast<const float4*>(&As[kk][ty * 8]);
      float4 a1 = *reinterpret_cast<const float4*>(&As[kk][ty * 8 + 4]);
      float4 b0 = *reinterpret_cast<const float4*>(&Bs[kk][tx * 4]);
      float a[8] = {a0.x, a0.y, a0.z, a0.w, a1.x, a1.y, a1.z, a1.w};
      float b[4] = {b0.x, b0.y, b0.z, b0.w};
      #pragma unroll
      for (int i = 0; i < 8; ++i)
        #pragma unroll
        for (int j = 0; j < 4; ++j) acc[i][j] += a[i] * b[j];
    }
    __syncthreads();
  }
  #pragma unroll
  for (int i = 0; i < 8; ++i) {
    int gm = bm + ty * 8 + i;
    int hw = gm & 4095;
    int h = hw >> 6, w = hw & 63;
    #pragma unroll
    for (int j = 0; j < 4; ++j) {
      int gn = bn + tx * 4 + j;
      float pos = (gn < 128) ? py[h * 128 + gn] : px[w * 128 + gn - 128];
      C[(size_t)gm * N + gn] = acc[i][j] + bcomb[gn] + pos;
    }
  }
}

// im2col for 3x3 pad-1 conv on channel-last (b,hw,c) input
__global__ __launch_bounds__(256)
void k_im2col(const float* __restrict__ y, float* __restrict__ col) {
  int m = blockIdx.x;          // (b*4096 + hw)
  int b = m >> 12, hw = m & 4095;
  int h = hw >> 6, w = hw & 63;
  int i = threadIdx.x;
  float* out = col + (size_t)m * KP1 + i * 9;
  #pragma unroll
  for (int ky = 0; ky < 3; ++ky)
    #pragma unroll
    for (int kx = 0; kx < 3; ++kx) {
      int hh = h + ky - 1, ww = w + kx - 1;
      float v = 0.f;
      if (hh >= 0 && hh < 64 && ww >= 0 && ww < 64)
        v = y[((size_t)(b << 12) + (hh << 6) + ww) * DM + i];
      out[ky * 3 + kx] = v;
    }
}

// queries = q_embed + q_pos (broadcast over batch), boxes init
__global__ __launch_bounds__(256)
void k_qinit(const float* __restrict__ q_embed, const float* __restrict__ q_pos,
             const float* __restrict__ boxes0, float* __restrict__ queries,
             float* __restrict__ boxes) {
  int m = blockIdx.x;          // 0..599
  int q = m % NQ;
  int d = threadIdx.x;
  queries[m * DM + d] = q_embed[q * DM + d] + q_pos[q * DM + d];
  if (d < 4) boxes[m * 4 + d] = boxes0[m * 4 + d];
}

// ro = tanh(h1 @ w_r2^T + b_r2)*0.5 ; ref = clip(boxes[:2] + ro, 0, 1)
__global__ __launch_bounds__(256)
void k_refpts(const float* __restrict__ h1, const float* __restrict__ boxes,
              const float* __restrict__ w_r2, const float* __restrict__ b_r2,
              float* __restrict__ ref) {
  int m = blockIdx.x;
  int g = threadIdx.x >> 4;       // 0..15 output index
  int lane16 = threadIdx.x & 15;
  float s = 0.f;
  for (int d = lane16; d < DM; d += 16)
    s += h1[m * DM + d] * w_r2[g * DM + d];
  #pragma unroll
  for (int off = 8; off > 0; off >>= 1)
    s += __shfl_down_sync(0xffffffffu, s, off, 16);
  __shared__ float ro_s[16];
  if (lane16 == 0) ro_s[g] = tanhf(s + b_r2[g]) * 0.5f;
  __syncthreads();
  if (threadIdx.x < 16) {
    int p = threadIdx.x >> 1, j = threadIdx.x & 1;
    float v = boxes[m * 4 + j] + ro_s[p * 2 + j];
    ref[(m * NP + p) * 2 + j] = fminf(fmaxf(v, 0.f), 1.f);
  }
}

// bilinear sampling of feat0 (channel-last) into flat (M=4800, K=2304)
__global__ __launch_bounds__(256)
void k_sample(const float* __restrict__ f0, const float* __restrict__ ref,
              float* __restrict__ flat) {
  int blk = blockIdx.x;            // 43200 = 600*8*9
  int kk = blk % 9;
  int rest = blk / 9;              // (b*300+q)*8 + p
  int p = rest & 7, m = rest >> 3;
  int b = (m >= NQ) ? 1 : 0;
  float rx = ref[(m * NP + p) * 2 + 0];
  float ry = ref[(m * NP + p) * 2 + 1];
  float oy = (float)(kk / 3 - 1), ox = (float)(kk % 3 - 1);
  float x = fminf(fmaxf((rx + ox * (1.f / 64.f)) * 63.f, 0.f), 63.f);
  float y = fminf(fmaxf((ry + oy * (1.f / 64.f)) * 63.f, 0.f), 63.f);
  float x0 = floorf(x), y0 = floorf(y);
  float wx = x - x0, wy = y - y0;
  int x0i = (int)x0, y0i = (int)y0;
  int x1i = min(x0i + 1, 63), y1i = min(y0i + 1, 63);
  int c = threadIdx.x;
  const float* f = f0 + (size_t)b * HWSZ * DM;
  float v00 = f[((y0i << 6) + x0i) * DM + c];
  float v01 = f[((y0i << 6) + x1i) * DM + c];
  float v10 = f[((y1i << 6) + x0i) * DM + c];
  float v11 = f[((y1i << 6) + x1i) * DM + c];
  float v = v00 * (1.f - wx) * (1.f - wy) + v01 * wx * (1.f - wy)
          + v10 * (1.f - wx) * wy + v11 * wx * wy;
  flat[(size_t)rest * KP1 + kk * DM + c] = v;
}

// mean over NP points
__global__ __launch_bounds__(256)
void k_mean(const float* __restrict__ pv, float* __restrict__ kvpre) {
  int m = blockIdx.x, d = threadIdx.x;
  float s = 0.f;
  #pragma unroll
  for (int p = 0; p < NP; ++p) s += pv[(size_t)(m * NP + p) * DM + d];
  kvpre[m * DM + d] = s * (1.f / NP);
}

// kvT[b][d][k] = kv[b][k][d]
__global__ __launch_bounds__(256)
void k_kvT(const float* __restrict__ kv, float* __restrict__ kvT) {
  int m = blockIdx.x;          // (b*300 + k)
  int b = (m >= NQ) ? 1 : 0;
  int k = m - b * NQ;
  int d = threadIdx.x;
  kvT[((size_t)b * DM + d) * NQ + k] = kv[(size_t)m * DM + d];
}

__global__ __launch_bounds__(512)
void k_softmax(float* __restrict__ S) {
  int m = blockIdx.x;
  int b = (m >= NQ) ? 1 : 0;
  float* row = S + (size_t)b * NQ * NQ + (size_t)(m - b * NQ) * NQ;
  int t = threadIdx.x;
  __shared__ float red[512];
  float v = (t < NQ) ? row[t] * 0.0625f : -1e30f;
  red[t] = v; __syncthreads();
  for (int s = 256; s > 0; s >>= 1) { if (t < s) red[t] = fmaxf(red[t], red[t + s]); __syncthreads(); }
  float mx = red[0]; __syncthreads();
  float e = (t < NQ) ? expf(v - mx) : 0.f;
  red[t] = e; __syncthreads();
  for (int s = 256; s > 0; s >>= 1) { if (t < s) red[t] += red[t + s]; __syncthreads(); }
  float inv = 1.f / red[0];
  if (t < NQ) row[t] = e * inv;
}

// box head epilogue: delta = sigmoid(hb @ w_b2^T + b_b2); box update
__global__ __launch_bounds__(128)
void k_box(const float* __restrict__ hb, const float* __restrict__ w_b2,
           const float* __restrict__ b_b2, float* __restrict__ boxes) {
  int m = blockIdx.x;
  int wj = threadIdx.x >> 5, lane = threadIdx.x & 31;
  float s = 0.f;
  for (int d = lane; d < DM; d += 32) s += hb[m * DM + d] * w_b2[wj * DM + d];
  #pragma unroll
  for (int off = 16; off > 0; off >>= 1) s += __shfl_down_sync(0xffffffffu, s, off);
  if (lane == 0) {
    float delta = 1.f / (1.f + expf(-(s + b_b2[wj])));
    float nb = boxes[m * 4 + wj] + 0.1f * tanhf(delta - 0.5f);
    boxes[m * 4 + wj] = fminf(fmaxf(nb, 0.f), 1.f);
  }
}

__global__ __launch_bounds__(256)
void k_logits(const float* __restrict__ queries, const float* __restrict__ w_cls,
              const float* __restrict__ b_cls, float* __restrict__ out) {
  int m = blockIdx.x, t = threadIdx.x;
  __shared__ float red[256];
  red[t] = queries[m * DM + t] * w_cls[t];
  __syncthreads();
  for (int s = 128; s > 0; s >>= 1) { if (t < s) red[t] += red[t + s]; __syncthreads(); }
  if (t == 0) out[m] = red[0] + b_cls[0];
}

__global__ __launch_bounds__(256)
void k_copyboxes(const float* __restrict__ boxes, float* __restrict__ out) {
  int i = blockIdx.x * 256 + threadIdx.x;
  if (i < MQ * 4) out[MQ + i] = boxes[i];
}

// ---------------------------------------------------------------------------
static inline dim3 ggrid(int M, int N) { return dim3((N + 63) / 64, (M + 127) / 128); }

extern "C" void kernel_launch(void* const* d_in, const int* in_sizes, int n_in,
                              void* d_out, int out_size) {
  const float* feat   = (const float*)d_in[0];
  const float* boxes0 = (const float*)d_in[1];
  const float* w_tf   = (const float*)d_in[2];
  const float* b_tf   = (const float*)d_in[3];
  const float* w_in   = (const float*)d_in[4];
  const float* b_in   = (const float*)d_in[5];
  const float* w_lat  = (const float*)d_in[6];
  const float* b_lat  = (const float*)d_in[7];
  const float* w_sm   = (const float*)d_in[8];
  const float* b_sm   = (const float*)d_in[9];
  const float* q_embed= (const float*)d_in[10];
  const float* q_pos  = (const float*)d_in[11];
  const float* Wq     = (const float*)d_in[12];
  const float* bq     = (const float*)d_in[13];
  const float* Wo     = (const float*)d_in[14];
  const float* bo     = (const float*)d_in[15];
  const float* Wp1    = (const float*)d_in[16];
  const float* bp1    = (const float*)d_in[17];
  const float* Wp2    = (const float*)d_in[18];
  const float* bp2    = (const float*)d_in[19];
  const float* w_r1   = (const float*)d_in[20];
  const float* b_r1   = (const float*)d_in[21];
  const float* w_r2   = (const float*)d_in[22];
  const float* b_r2   = (const float*)d_in[23];
  const float* w_b1   = (const float*)d_in[24];
  const float* b_b1   = (const float*)d_in[25];
  const float* w_b2   = (const float*)d_in[26];
  const float* b_b2   = (const float*)d_in[27];
  const float* w_cls  = (const float*)d_in[28];
  const float* b_cls  = (const float*)d_in[29];
  float* out = (float*)d_out;

  float* base = nullptr;
  cudaGetSymbolAddress((void**)&base, g_buf);
  float* p_wcomb = base + O_WCOMB;
  float* p_bcomb = base + O_BCOMB;
  float* p_py    = base + O_PY;
  float* p_px    = base + O_PX;
  float* p_x     = base + O_X;
  float* p_lat   = base + O_LAT;
  float* p_col   = base + O_COL;
  float* p_f0    = base + O_F0;
  float* p_q     = base + O_Q;
  float* p_h1    = base + O_H1;
  float* p_ref   = base + O_REF;
  float* p_flat  = base + O_FLAT;
  float* p_pv    = base + O_PV;
  float* p_kvp   = base + O_KVP;
  float* p_kv    = base + O_KV;
  float* p_qp    = base + O_QP;
  float* p_kvT   = base + O_KVT;
  float* p_S     = base + O_S;
  float* p_ao    = base + O_AO;
  float* p_hb    = base + O_HB;
  float* p_box   = base + O_BOX;

  // ---- stem (conv3d + mean_T + in-proj fused into one GEMM) + pos ----
  k_wcomb<<<(256 * 512 + 255) / 256, 256>>>(w_tf, w_in, b_tf, b_in, p_wcomb, p_bcomb);
  k_pos<<<(2 * 64 * 128 + 255) / 256, 256>>>(p_py, p_px);
  k_stem<<<ggrid(MROWS, DM), 256>>>(feat, p_wcomb, p_bcomb, p_py, p_px, p_x);

  // ---- scale-1 feature only (scales 2,4 are dead code in the reference) ----
  sgemm_nt<0><<<ggrid(MROWS, DM), 256>>>(p_x, w_lat, b_lat, nullptr, p_lat, MROWS, DM, DM);
  k_im2col<<<MROWS, 256>>>(p_lat, p_col);
  sgemm_nt<0><<<ggrid(MROWS, DM), 256>>>(p_col, w_sm, b_sm, nullptr, p_f0, MROWS, DM, KP1);

  // ---- decoder init ----
  k_qinit<<<MQ, 256>>>(q_embed, q_pos, boxes0, p_q, p_box);

  for (int l = 0; l < NLAY; ++l) {
    const float* Wq_l  = Wq  + (size_t)l * DM * DM;
    const float* bq_l  = bq  + (size_t)l * DM;
    const float* Wo_l  = Wo  + (size_t)l * DM * DM;
    const float* bo_l  = bo  + (size_t)l * DM;
    const float* Wp1_l = Wp1 + (size_t)l * DM * KP1;
    const float* bp1_l = bp1 + (size_t)l * DM;
    const float* Wp2_l = Wp2 + (size_t)l * DM * DM;
    const float* bp2_l = bp2 + (size_t)l * DM;

    // reference-point head
    sgemm_nt<1><<<ggrid(MQ, DM), 256>>>(p_q, w_r1, b_r1, nullptr, p_h1, MQ, DM, DM);
    k_refpts<<<MQ, 256>>>(p_h1, p_box, w_r2, b_r2, p_ref);

    // bilinear patch sampling -> flat (4800 x 2304)
    k_sample<<<MQ * NP * 9, 256>>>(p_f0, p_ref, p_flat);

    // patch value MLP (big GEMM), then mean over points, then Wp2
    sgemm_nt<1><<<ggrid(MS, DM), 256>>>(p_flat, Wp1_l, bp1_l, nullptr, p_pv, MS, DM, KP1);
    k_mean<<<MQ, 256>>>(p_pv, p_kvp);
    sgemm_nt<0><<<ggrid(MQ, DM), 256>>>(p_kvp, Wp2_l, bp2_l, nullptr, p_kv, MQ, DM, DM);

    // attention
    sgemm_nt<0><<<ggrid(MQ, DM), 256>>>(p_q, Wq_l, bq_l, nullptr, p_qp, MQ, DM, DM);
    k_kvT<<<MQ, 256>>>(p_kv, p_kvT);
    for (int b = 0; b < BATCH; ++b)
      sgemm_nt<0><<<ggrid(NQ, NQ), 256>>>(p_qp + (size_t)b * NQ * DM,
                                          p_kv + (size_t)b * NQ * DM,
                                          nullptr, nullptr,
                                          p_S + (size_t)b * NQ * NQ, NQ, NQ, DM);
    k_softmax<<<MQ, 512>>>(p_S);
    for (int b = 0; b < BATCH; ++b)
      sgemm_nt<0><<<ggrid(NQ, DM), 256>>>(p_S + (size_t)b * NQ * NQ,
                                          p_kvT + (size_t)b * DM * NQ,
                                          nullptr, nullptr,
                                          p_ao + (size_t)b * NQ * DM, NQ, DM, NQ);
    // residual update of queries
    sgemm_nt<2><<<ggrid(MQ, DM), 256>>>(p_ao, Wo_l, bo_l, p_q, p_q, MQ, DM, DM);

    // box head
    sgemm_nt<1><<<ggrid(MQ, DM), 256>>>(p_q, w_b1, b_b1, nullptr, p_hb, MQ, DM, DM);
    k_box<<<MQ, 128>>>(p_hb, w_b2, b_b2, p_box);
  }

  // ---- outputs: [logits(600), boxes(2400)] ----
  k_logits<<<MQ, 256>>>(p_q, w_cls, b_cls, out);
  k_copyboxes<<<(MQ * 4 + 255) / 256, 256>>>(p_box, out);
}

// round 2
// speedup vs baseline: 1.1201x; 1.1201x over previous
#include <cuda_runtime.h>
#include <math.h>
#include <stdint.h>

// ---------------------------------------------------------------------------
// Problem constants
// ---------------------------------------------------------------------------
#define HH 64
#define WW 64
#define HWSZ 4096
#define CIN 128
#define TT 4
#define DM 256
#define NQ 300
#define NP 8
#define NLAY 6
#define BATCH 2
#define MROWS (BATCH*HWSZ)      // 8192 spatial rows
#define MQ (BATCH*NQ)           // 600 query rows
#define MS (MQ*NP)              // 4800 sample rows
#define KP1 2304                // 3*3*256

// ---------------------------------------------------------------------------
// Scratch
// ---------------------------------------------------------------------------
constexpr size_t O_WCOMB = 0;                        // 256*512
constexpr size_t O_BCOMB = O_WCOMB + 256*512;        // 256
constexpr size_t O_PY    = O_BCOMB + 256;            // 64*128
constexpr size_t O_PX    = O_PY + 64*128;            // 64*128
constexpr size_t O_X     = O_PX + 64*128;            // 8192*256
constexpr size_t O_LAT   = O_X + (size_t)MROWS*DM;   // 8192*256
constexpr size_t O_COL   = O_LAT + (size_t)MROWS*DM; // 8192*2304
constexpr size_t O_F0    = O_COL + (size_t)MROWS*KP1;// 8192*256
constexpr size_t O_Q     = O_F0 + (size_t)MROWS*DM;  // 600*256
constexpr size_t O_H1    = O_Q + MQ*DM;
constexpr size_t O_REF   = O_H1 + MQ*DM;             // 600*8*2
constexpr size_t O_FLAT  = O_REF + MQ*NP*2;          // 4800*2304
constexpr size_t O_PV    = O_FLAT + (size_t)MS*KP1;  // 4800*256
constexpr size_t O_KVP   = O_PV + (size_t)MS*DM;
constexpr size_t O_KV    = O_KVP + MQ*DM;
constexpr size_t O_QP    = O_KV + MQ*DM;
constexpr size_t O_KVT   = O_QP + MQ*DM;             // 2*256*300
constexpr size_t O_S     = O_KVT + MQ*DM;            // 2*300*300
constexpr size_t O_AO    = O_S + BATCH*NQ*NQ;
constexpr size_t O_HB    = O_AO + MQ*DM;
constexpr size_t O_BOX   = O_HB + MQ*DM;             // 600*4
constexpr size_t G_TOTAL = O_BOX + MQ*4;

__device__ float g_buf[G_TOTAL];

// ---------------------------------------------------------------------------
// TF32 helpers
// ---------------------------------------------------------------------------
__device__ __forceinline__ uint32_t f2tf32(float x) {
  uint32_t r;
  asm("cvt.rna.tf32.f32 %0, %1;" : "=r"(r) : "f"(x));
  return r;
}
__device__ __forceinline__ void split_tf32(float x, uint32_t& hi, uint32_t& lo) {
  hi = f2tf32(x);
  lo = f2tf32(x - __uint_as_float(hi));
}
__device__ __forceinline__ void mma_tf32(float* c, const uint32_t* a, const uint32_t* b) {
  asm volatile(
    "mma.sync.aligned.m16n8k8.row.col.f32.tf32.tf32.f32 "
    "{%0,%1,%2,%3},{%4,%5,%6,%7},{%8,%9},{%0,%1,%2,%3};"
    : "+f"(c[0]), "+f"(c[1]), "+f"(c[2]), "+f"(c[3])
    : "r"(a[0]), "r"(a[1]), "r"(a[2]), "r"(a[3]), "r"(b[0]), "r"(b[1]));
}

// ---------------------------------------------------------------------------
// 3xTF32 GEMM: C[M,N] = A[M,K] @ Bw[N,K]^T, fp32-accurate via hi/lo split.
// Block 128x64, 8 warps of 32x32, BK=16. EPI: 0=+bias, 1=+bias+relu, 2=+bias+res
// ---------------------------------------------------------------------------
template<int EPI>
__global__ __launch_bounds__(256)
void gemm_tf32(const float* __restrict__ A, const float* __restrict__ Bw,
               const float* __restrict__ bias, const float* __restrict__ res,
               float* __restrict__ C, int M, int N, int K) {
  const int BM = 128, BN = 64, BK = 16, PAD = 20;
  __shared__ uint32_t Ah[BM][PAD], Al[BM][PAD];
  __shared__ uint32_t Bh[BN][PAD], Bl[BN][PAD];

  int tid = threadIdx.x;
  int bm = blockIdx.y * BM, bn = blockIdx.x * BN;
  int lane = tid & 31, warp = tid >> 5;
  int wm = (warp >> 1) * 32, wn = (warp & 1) * 32;
  int gid = lane >> 2, tig = lane & 3;

  float acc[2][4][4] = {};

  int Kpad = (K + BK - 1) / BK * BK;

  // prefetch registers (A: 2 float4, B: 1 float4 per thread)
  float4 pa[2], pb;
  int am[2], ak[2], bm_r, bk_r;
  {
    #pragma unroll
    for (int l = 0; l < 2; ++l) {
      int li = tid + l * 256;
      am[l] = li >> 2;              // 0..127
      ak[l] = (li & 3) * 4;         // 0,4,8,12
    }
    bm_r = tid >> 2;                // 0..63
    bk_r = (tid & 3) * 4;
  }

  auto loadA = [&](int k0, int l) -> float4 {
    float4 v = make_float4(0.f, 0.f, 0.f, 0.f);
    int gm = bm + am[l], gk = k0 + ak[l];
    if (gm < M) {
      if (gk + 3 < K) v = *reinterpret_cast<const float4*>(A + (size_t)gm * K + gk);
      else {
        float t[4] = {0.f, 0.f, 0.f, 0.f};
        #pragma unroll
        for (int e = 0; e < 4; ++e) if (gk + e < K) t[e] = A[(size_t)gm * K + gk + e];
        v = make_float4(t[0], t[1], t[2], t[3]);
      }
    }
    return v;
  };
  auto loadB = [&](int k0) -> float4 {
    float4 v = make_float4(0.f, 0.f, 0.f, 0.f);
    int gn = bn + bm_r, gk = k0 + bk_r;
    if (gn < N) {
      if (gk + 3 < K) v = *reinterpret_cast<const float4*>(Bw + (size_t)gn * K + gk);
      else {
        float t[4] = {0.f, 0.f, 0.f, 0.f};
        #pragma unroll
        for (int e = 0; e < 4; ++e) if (gk + e < K) t[e] = Bw[(size_t)gn * K + gk + e];
        v = make_float4(t[0], t[1], t[2], t[3]);
      }
    }
    return v;
  };

  pa[0] = loadA(0, 0); pa[1] = loadA(0, 1); pb = loadB(0);

  for (int k0 = 0; k0 < Kpad; k0 += BK) {
    // store prefetched tile to smem with tf32 hi/lo split
    #pragma unroll
    for (int l = 0; l < 2; ++l) {
      float v[4] = {pa[l].x, pa[l].y, pa[l].z, pa[l].w};
      #pragma unroll
      for (int e = 0; e < 4; ++e)
        split_tf32(v[e], Ah[am[l]][ak[l] + e], Al[am[l]][ak[l] + e]);
    }
    {
      float v[4] = {pb.x, pb.y, pb.z, pb.w};
      #pragma unroll
      for (int e = 0; e < 4; ++e)
        split_tf32(v[e], Bh[bm_r][bk_r + e], Bl[bm_r][bk_r + e]);
    }
    __syncthreads();

    if (k0 + BK < Kpad) {
      pa[0] = loadA(k0 + BK, 0); pa[1] = loadA(k0 + BK, 1); pb = loadB(k0 + BK);
    }

    #pragma unroll
    for (int ks = 0; ks < 2; ++ks) {
      int k8 = ks * 8;
      uint32_t ah[2][4], al[2][4];
      #pragma unroll
      for (int i = 0; i < 2; ++i) {
        int r = wm + 16 * i + gid;
        ah[i][0] = Ah[r][k8 + tig];     al[i][0] = Al[r][k8 + tig];
        ah[i][1] = Ah[r + 8][k8 + tig]; al[i][1] = Al[r + 8][k8 + tig];
        ah[i][2] = Ah[r][k8 + tig + 4]; al[i][2] = Al[r][k8 + tig + 4];
        ah[i][3] = Ah[r + 8][k8 + tig + 4]; al[i][3] = Al[r + 8][k8 + tig + 4];
      }
      uint32_t bh[4][2], bl[4][2];
      #pragma unroll
      for (int j = 0; j < 4; ++j) {
        int r = wn + 8 * j + gid;
        bh[j][0] = Bh[r][k8 + tig];     bl[j][0] = Bl[r][k8 + tig];
        bh[j][1] = Bh[r][k8 + tig + 4]; bl[j][1] = Bl[r][k8 + tig + 4];
      }
      #pragma unroll
      for (int i = 0; i < 2; ++i)
        #pragma unroll
        for (int j = 0; j < 4; ++j) {
          mma_tf32(acc[i][j], ah[i], bh[j]);
          mma_tf32(acc[i][j], ah[i], bl[j]);
          mma_tf32(acc[i][j], al[i], bh[j]);
        }
    }
    __syncthreads();
  }

  // epilogue
  #pragma unroll
  for (int i = 0; i < 2; ++i) {
    #pragma unroll
    for (int j = 0; j < 4; ++j) {
      int c0 = bn + wn + 8 * j + 2 * tig;
      #pragma unroll
      for (int half = 0; half < 2; ++half) {
        int gm = bm + wm + 16 * i + gid + 8 * half;
        if (gm >= M) continue;
        #pragma unroll
        for (int e = 0; e < 2; ++e) {
          int gn = c0 + e;
          if (gn >= N) continue;
          float v = acc[i][j][half * 2 + e] + (bias ? bias[gn] : 0.f);
          if (EPI == 1) v = fmaxf(v, 0.f);
          if (EPI == 2) v += res[(size_t)gm * N + gn];
          C[(size_t)gm * N + gn] = v;
        }
      }
    }
  }
}

// ---------------------------------------------------------------------------
// Stem weight combine
// ---------------------------------------------------------------------------
__global__ __launch_bounds__(256)
void k_wcomb(const float* __restrict__ w_tf, const float* __restrict__ w_in,
             const float* __restrict__ b_tf, const float* __restrict__ b_in,
             float* __restrict__ wcomb, float* __restrict__ bcomb) {
  int idx = blockIdx.x * 256 + threadIdx.x;
  if (idx < 256 * 512) {
    int dm = idx >> 9, k = idx & 511, i = k >> 2, t = k & 3;
    float s = 0.f;
    for (int c = 0; c < CIN; ++c) {
      const float* wt = w_tf + (c * CIN + i) * 3;
      float we = wt[1];
      if (t != 3) we += wt[0];
      if (t != 0) we += wt[2];
      s += w_in[dm * CIN + c] * we;
    }
    wcomb[idx] = 0.25f * s;
  }
  if (idx < 256) {
    float s = b_in[idx];
    for (int c = 0; c < CIN; ++c) s += w_in[idx * CIN + c] * b_tf[c];
    bcomb[idx] = s;
  }
}

__global__ __launch_bounds__(256)
void k_pos(float* __restrict__ py, float* __restrict__ px) {
  int idx = blockIdx.x * 256 + threadIdx.x;
  if (idx >= 2 * 64 * 128) return;
  int half = idx / (64 * 128);
  int r = idx - half * (64 * 128);
  int hw = r >> 7, c = r & 127;
  float dim_t = powf(10000.f, 2.f * (float)(c >> 2) / 64.f);
  float v = (float)(hw + 1) / (64.f + 1e-6f) * 2.f * 3.14159265358979323846f;
  float a = v / dim_t;
  float o = (c & 1) ? cosf(a) : sinf(a);
  if (half) px[r] = o; else py[r] = o;
}

// ---------------------------------------------------------------------------
// Stem GEMM (fp32, gathered A)
// ---------------------------------------------------------------------------
__global__ __launch_bounds__(256)
void k_stem(const float* __restrict__ feat, const float* __restrict__ wcomb,
            const float* __restrict__ bcomb, const float* __restrict__ py,
            const float* __restrict__ px, float* __restrict__ C) {
  const int BM = 128, BN = 64, BK = 16, K = 512, N = 256;
  __shared__ float As[BK][BM + 4];
  __shared__ float Bs[BK][BN + 4];
  int bm = blockIdx.y * BM, bn = blockIdx.x * BN;
  int tid = threadIdx.x;
  int tx = tid & 15, ty = tid >> 4;
  float acc[8][4] = {};
  for (int k0 = 0; k0 < K; k0 += BK) {
    #pragma unroll
    for (int l = 0; l < 8; ++l) {
      int e = tid + l * 256;
      int k = e >> 7, mm = e & 127;
      int gm = bm + mm, gk = k0 + k;
      int b = gm >> 12, hw = gm & 4095;
      int i = gk >> 2, t = gk & 3;
      As[k][mm] = feat[(size_t)(((b << 2) + t) * CIN + i) * HWSZ + hw];
    }
    {
      int m = tid >> 2, kq = (tid & 3) * 4;
      float4 v = *reinterpret_cast<const float4*>(wcomb + (size_t)(bn + m) * K + k0 + kq);
      Bs[kq + 0][m] = v.x; Bs[kq + 1][m] = v.y;
      Bs[kq + 2][m] = v.z; Bs[kq + 3][m] = v.w;
    }
    __syncthreads();
    #pragma unroll
    for (int kk = 0; kk < BK; ++kk) {
      float4 a0 = *reinterpret_cast<const float4*>(&As[kk][ty * 8]);
      float4 a1 = *reinterpret_cast<const float4*>(&As[kk][ty * 8 + 4]);
      float4 b0 = *reinterpret_cast<const float4*>(&Bs[kk][tx * 4]);
      float a[8] = {a0.x, a0.y, a0.z, a0.w, a1.x, a1.y, a1.z, a1.w};
      float b[4] = {b0.x, b0.y, b0.z, b0.w};
      #pragma unroll
      for (int i = 0; i < 8; ++i)
        #pragma unroll
        for (int j = 0; j < 4; ++j) acc[i][j] += a[i] * b[j];
    }
    __syncthreads();
  }
  #pragma unroll
  for (int i = 0; i < 8; ++i) {
    int gm = bm + ty * 8 + i;
    int hw = gm & 4095;
    int h = hw >> 6, w = hw & 63;
    #pragma unroll
    for (int j = 0; j < 4; ++j) {
      int gn = bn + tx * 4 + j;
      float pos = (gn < 128) ? py[h * 128 + gn] : px[w * 128 + gn - 128];
      C[(size_t)gm * N + gn] = acc[i][j] + bcomb[gn] + pos;
    }
  }
}

// im2col for 3x3 pad-1 conv on channel-last input
__global__ __launch_bounds__(256)
void k_im2col(const float* __restrict__ y, float* __restrict__ col) {
  int m = blockIdx.x;
  int b = m >> 12, hw = m & 4095;
  int h = hw >> 6, w = hw & 63;
  int i = threadIdx.x;
  float* out = col + (size_t)m * KP1 + i * 9;
  #pragma unroll
  for (int ky = 0; ky < 3; ++ky)
    #pragma unroll
    for (int kx = 0; kx < 3; ++kx) {
      int hh = h + ky - 1, ww = w + kx - 1;
      float v = 0.f;
      if (hh >= 0 && hh < 64 && ww >= 0 && ww < 64)
        v = y[((size_t)(b << 12) + (hh << 6) + ww) * DM + i];
      out[ky * 3 + kx] = v;
    }
}

__global__ __launch_bounds__(256)
void k_qinit(const float* __restrict__ q_embed, const float* __restrict__ q_pos,
             const float* __restrict__ boxes0, float* __restrict__ queries,
             float* __restrict__ boxes) {
  int m = blockIdx.x;
  int q = m % NQ;
  int d = threadIdx.x;
  queries[m * DM + d] = q_embed[q * DM + d] + q_pos[q * DM + d];
  if (d < 4) boxes[m * 4 + d] = boxes0[m * 4 + d];
}

__global__ __launch_bounds__(256)
void k_refpts(const float* __restrict__ h1, const float* __restrict__ boxes,
              const float* __restrict__ w_r2, const float* __restrict__ b_r2,
              float* __restrict__ ref) {
  int m = blockIdx.x;
  int g = threadIdx.x >> 4;
  int lane16 = threadIdx.x & 15;
  float s = 0.f;
  for (int d = lane16; d < DM; d += 16)
    s += h1[m * DM + d] * w_r2[g * DM + d];
  #pragma unroll
  for (int off = 8; off > 0; off >>= 1)
    s += __shfl_down_sync(0xffffffffu, s, off, 16);
  __shared__ float ro_s[16];
  if (lane16 == 0) ro_s[g] = tanhf(s + b_r2[g]) * 0.5f;
  __syncthreads();
  if (threadIdx.x < 16) {
    int p = threadIdx.x >> 1, j = threadIdx.x & 1;
    float v = boxes[m * 4 + j] + ro_s[p * 2 + j];
    ref[(m * NP + p) * 2 + j] = fminf(fmaxf(v, 0.f), 1.f);
  }
}

__global__ __launch_bounds__(256)
void k_sample(const float* __restrict__ f0, const float* __restrict__ ref,
              float* __restrict__ flat) {
  int blk = blockIdx.x;
  int kk = blk % 9;
  int rest = blk / 9;
  int p = rest & 7, m = rest >> 3;
  int b = (m >= NQ) ? 1 : 0;
  float rx = ref[(m * NP + p) * 2 + 0];
  float ry = ref[(m * NP + p) * 2 + 1];
  float oy = (float)(kk / 3 - 1), ox = (float)(kk % 3 - 1);
  float x = fminf(fmaxf((rx + ox * (1.f / 64.f)) * 63.f, 0.f), 63.f);
  float y = fminf(fmaxf((ry + oy * (1.f / 64.f)) * 63.f, 0.f), 63.f);
  float x0 = floorf(x), y0 = floorf(y);
  float wx = x - x0, wy = y - y0;
  int x0i = (int)x0, y0i = (int)y0;
  int x1i = min(x0i + 1, 63), y1i = min(y0i + 1, 63);
  int c = threadIdx.x;
  const float* f = f0 + (size_t)b * HWSZ * DM;
  float v00 = f[((y0i << 6) + x0i) * DM + c];
  float v01 = f[((y0i << 6) + x1i) * DM + c];
  float v10 = f[((y1i << 6) + x0i) * DM + c];
  float v11 = f[((y1i << 6) + x1i) * DM + c];
  float v = v00 * (1.f - wx) * (1.f - wy) + v01 * wx * (1.f - wy)
          + v10 * (1.f - wx) * wy + v11 * wx * wy;
  flat[(size_t)rest * KP1 + kk * DM + c] = v;
}

__global__ __launch_bounds__(256)
void k_mean(const float* __restrict__ pv, float* __restrict__ kvpre) {
  int m = blockIdx.x, d = threadIdx.x;
  float s = 0.f;
  #pragma unroll
  for (int p = 0; p < NP; ++p) s += pv[(size_t)(m * NP + p) * DM + d];
  kvpre[m * DM + d] = s * (1.f / NP);
}

__global__ __launch_bounds__(256)
void k_kvT(const float* __restrict__ kv, float* __restrict__ kvT) {
  int m = blockIdx.x;
  int b = (m >= NQ) ? 1 : 0;
  int k = m - b * NQ;
  int d = threadIdx.x;
  kvT[((size_t)b * DM + d) * NQ + k] = kv[(size_t)m * DM + d];
}

__global__ __launch_bounds__(512)
void k_softmax(float* __restrict__ S) {
  int m = blockIdx.x;
  int b = (m >= NQ) ? 1 : 0;
  float* row = S + (size_t)b * NQ * NQ + (size_t)(m - b * NQ) * NQ;
  int t = threadIdx.x;
  __shared__ float red[512];
  float v = (t < NQ) ? row[t] * 0.0625f : -1e30f;
  red[t] = v; __syncthreads();
  for (int s = 256; s > 0; s >>= 1) { if (t < s) red[t] = fmaxf(red[t], red[t + s]); __syncthreads(); }
  float mx = red[0]; __syncthreads();
  float e = (t < NQ) ? expf(v - mx) : 0.f;
  red[t] = e; __syncthreads();
  for (int s = 256; s > 0; s >>= 1) { if (t < s) red[t] += red[t + s]; __syncthreads(); }
  float inv = 1.f / red[0];
  if (t < NQ) row[t] = e * inv;
}

__global__ __launch_bounds__(128)
void k_box(const float* __restrict__ hb, const float* __restrict__ w_b2,
           const float* __restrict__ b_b2, float* __restrict__ boxes) {
  int m = blockIdx.x;
  int wj = threadIdx.x >> 5, lane = threadIdx.x & 31;
  float s = 0.f;
  for (int d = lane; d < DM; d += 32) s += hb[m * DM + d] * w_b2[wj * DM + d];
  #pragma unroll
  for (int off = 16; off > 0; off >>= 1) s += __shfl_down_sync(0xffffffffu, s, off);
  if (lane == 0) {
    float delta = 1.f / (1.f + expf(-(s + b_b2[wj])));
    float nb = boxes[m * 4 + wj] + 0.1f * tanhf(delta - 0.5f);
    boxes[m * 4 + wj] = fminf(fmaxf(nb, 0.f), 1.f);
  }
}

__global__ __launch_bounds__(256)
void k_logits(const float* __restrict__ queries, const float* __restrict__ w_cls,
              const float* __restrict__ b_cls, float* __restrict__ out) {
  int m = blockIdx.x, t = threadIdx.x;
  __shared__ float red[256];
  red[t] = queries[m * DM + t] * w_cls[t];
  __syncthreads();
  for (int s = 128; s > 0; s >>= 1) { if (t < s) red[t] += red[t + s]; __syncthreads(); }
  if (t == 0) out[m] = red[0] + b_cls[0];
}

__global__ __launch_bounds__(256)
void k_copyboxes(const float* __restrict__ boxes, float* __restrict__ out) {
  int i = blockIdx.x * 256 + threadIdx.x;
  if (i < MQ * 4) out[MQ + i] = boxes[i];
}

// ---------------------------------------------------------------------------
static inline dim3 ggrid(int M, int N) { return dim3((N + 63) / 64, (M + 127) / 128); }

extern "C" void kernel_launch(void* const* d_in, const int* in_sizes, int n_in,
                              void* d_out, int out_size) {
  const float* feat   = (const float*)d_in[0];
  const float* boxes0 = (const float*)d_in[1];
  const float* w_tf   = (const float*)d_in[2];
  const float* b_tf   = (const float*)d_in[3];
  const float* w_in   = (const float*)d_in[4];
  const float* b_in   = (const float*)d_in[5];
  const float* w_lat  = (const float*)d_in[6];
  const float* b_lat  = (const float*)d_in[7];
  const float* w_sm   = (const float*)d_in[8];
  const float* b_sm   = (const float*)d_in[9];
  const float* q_embed= (const float*)d_in[10];
  const float* q_pos  = (const float*)d_in[11];
  const float* Wq     = (const float*)d_in[12];
  const float* bq     = (const float*)d_in[13];
  const float* Wo     = (const float*)d_in[14];
  const float* bo     = (const float*)d_in[15];
  const float* Wp1    = (const float*)d_in[16];
  const float* bp1    = (const float*)d_in[17];
  const float* Wp2    = (const float*)d_in[18];
  const float* bp2    = (const float*)d_in[19];
  const float* w_r1   = (const float*)d_in[20];
  const float* b_r1   = (const float*)d_in[21];
  const float* w_r2   = (const float*)d_in[22];
  const float* b_r2   = (const float*)d_in[23];
  const float* w_b1   = (const float*)d_in[24];
  const float* b_b1   = (const float*)d_in[25];
  const float* w_b2   = (const float*)d_in[26];
  const float* b_b2   = (const float*)d_in[27];
  const float* w_cls  = (const float*)d_in[28];
  const float* b_cls  = (const float*)d_in[29];
  float* out = (float*)d_out;

  float* base = nullptr;
  cudaGetSymbolAddress((void**)&base, g_buf);
  float* p_wcomb = base + O_WCOMB;
  float* p_bcomb = base + O_BCOMB;
  float* p_py    = base + O_PY;
  float* p_px    = base + O_PX;
  float* p_x     = base + O_X;
  float* p_lat   = base + O_LAT;
  float* p_col   = base + O_COL;
  float* p_f0    = base + O_F0;
  float* p_q     = base + O_Q;
  float* p_h1    = base + O_H1;
  float* p_ref   = base + O_REF;
  float* p_flat  = base + O_FLAT;
  float* p_pv    = base + O_PV;
  float* p_kvp   = base + O_KVP;
  float* p_kv    = base + O_KV;
  float* p_qp    = base + O_QP;
  float* p_kvT   = base + O_KVT;
  float* p_S     = base + O_S;
  float* p_ao    = base + O_AO;
  float* p_hb    = base + O_HB;
  float* p_box   = base + O_BOX;

  // ---- stem (conv3d + mean_T + in-proj fused) + pos ----
  k_wcomb<<<(256 * 512 + 255) / 256, 256>>>(w_tf, w_in, b_tf, b_in, p_wcomb, p_bcomb);
  k_pos<<<(2 * 64 * 128 + 255) / 256, 256>>>(p_py, p_px);
  k_stem<<<ggrid(MROWS, DM), 256>>>(feat, p_wcomb, p_bcomb, p_py, p_px, p_x);

  // ---- scale-1 feature only (scales 2,4 dead in reference) ----
  gemm_tf32<0><<<ggrid(MROWS, DM), 256>>>(p_x, w_lat, b_lat, nullptr, p_lat, MROWS, DM, DM);
  k_im2col<<<MROWS, 256>>>(p_lat, p_col);
  gemm_tf32<0><<<ggrid(MROWS, DM), 256>>>(p_col, w_sm, b_sm, nullptr, p_f0, MROWS, DM, KP1);

  // ---- decoder init ----
  k_qinit<<<MQ, 256>>>(q_embed, q_pos, boxes0, p_q, p_box);

  for (int l = 0; l < NLAY; ++l) {
    const float* Wq_l  = Wq  + (size_t)l * DM * DM;
    const float* bq_l  = bq  + (size_t)l * DM;
    const float* Wo_l  = Wo  + (size_t)l * DM * DM;
    const float* bo_l  = bo  + (size_t)l * DM;
    const float* Wp1_l = Wp1 + (size_t)l * DM * KP1;
    const float* bp1_l = bp1 + (size_t)l * DM;
    const float* Wp2_l = Wp2 + (size_t)l * DM * DM;
    const float* bp2_l = bp2 + (size_t)l * DM;

    gemm_tf32<1><<<ggrid(MQ, DM), 256>>>(p_q, w_r1, b_r1, nullptr, p_h1, MQ, DM, DM);
    k_refpts<<<MQ, 256>>>(p_h1, p_box, w_r2, b_r2, p_ref);

    k_sample<<<MQ * NP * 9, 256>>>(p_f0, p_ref, p_flat);

    gemm_tf32<1><<<ggrid(MS, DM), 256>>>(p_flat, Wp1_l, bp1_l, nullptr, p_pv, MS, DM, KP1);
    k_mean<<<MQ, 256>>>(p_pv, p_kvp);
    gemm_tf32<0><<<ggrid(MQ, DM), 256>>>(p_kvp, Wp2_l, bp2_l, nullptr, p_kv, MQ, DM, DM);

    gemm_tf32<0><<<ggrid(MQ, DM), 256>>>(p_q, Wq_l, bq_l, nullptr, p_qp, MQ, DM, DM);
    k_kvT<<<MQ, 256>>>(p_kv, p_kvT);
    for (int b = 0; b < BATCH; ++b)
      gemm_tf32<0><<<ggrid(NQ, NQ), 256>>>(p_qp + (size_t)b * NQ * DM,
                                           p_kv + (size_t)b * NQ * DM,
                                           nullptr, nullptr,
                                           p_S + (size_t)b * NQ * NQ, NQ, NQ, DM);
    k_softmax<<<MQ, 512>>>(p_S);
    for (int b = 0; b < BATCH; ++b)
      gemm_tf32<0><<<ggrid(NQ, DM), 256>>>(p_S + (size_t)b * NQ * NQ,
                                           p_kvT + (size_t)b * DM * NQ,
                                           nullptr, nullptr,
                                           p_ao + (size_t)b * NQ * DM, NQ, DM, NQ);
    gemm_tf32<2><<<ggrid(MQ, DM), 256>>>(p_ao, Wo_l, bo_l, p_q, p_q, MQ, DM, DM);

    gemm_tf32<1><<<ggrid(MQ, DM), 256>>>(p_q, w_b1, b_b1, nullptr, p_hb, MQ, DM, DM);
    k_box<<<MQ, 128>>>(p_hb, w_b2, b_b2, p_box);
  }

  k_logits<<<MQ, 256>>>(p_q, w_cls, b_cls, out);
  k_copyboxes<<<(MQ * 4 + 255) / 256, 256>>>(p_box, out);
}

// round 3
// speedup vs baseline: 1.3602x; 1.2144x over previous
#include <cuda_runtime.h>
#include <math.h>
#include <stdint.h>

// ---------------------------------------------------------------------------
// Problem constants
// ---------------------------------------------------------------------------
#define HH 64
#define WW 64
#define HWSZ 4096
#define CIN 128
#define TT 4
#define DM 256
#define NQ 300
#define NP 8
#define NLAY 6
#define BATCH 2
#define MROWS (BATCH*HWSZ)      // 8192 spatial rows
#define MQ (BATCH*NQ)           // 600 query rows
#define MS (MQ*NP)              // 4800 sample rows
#define KP1 2304                // 3*3*256

// ---------------------------------------------------------------------------
// Scratch
// ---------------------------------------------------------------------------
constexpr size_t O_WCOMB = 0;                        // 256*512
constexpr size_t O_BCOMB = O_WCOMB + 256*512;        // 256
constexpr size_t O_PY    = O_BCOMB + 256;            // 64*128
constexpr size_t O_PX    = O_PY + 64*128;            // 64*128
constexpr size_t O_X     = O_PX + 64*128;            // 8192*256
constexpr size_t O_LAT   = O_X + (size_t)MROWS*DM;   // 8192*256
constexpr size_t O_COL   = O_LAT + (size_t)MROWS*DM; // 8192*2304
constexpr size_t O_F0    = O_COL + (size_t)MROWS*KP1;// 8192*256
constexpr size_t O_Q     = O_F0 + (size_t)MROWS*DM;  // 600*256
constexpr size_t O_H1    = O_Q + MQ*DM;
constexpr size_t O_REF   = O_H1 + MQ*DM;             // 600*8*2
constexpr size_t O_FLAT  = O_REF + MQ*NP*2;          // 4800*2304
constexpr size_t O_PV    = O_FLAT + (size_t)MS*KP1;  // 4800*256
constexpr size_t O_KVP   = O_PV + (size_t)MS*DM;
constexpr size_t O_KV    = O_KVP + MQ*DM;
constexpr size_t O_QP    = O_KV + MQ*DM;
constexpr size_t O_KVT   = O_QP + MQ*DM;             // 2*256*300
constexpr size_t O_S     = O_KVT + MQ*DM;            // 2*300*300
constexpr size_t O_AO    = O_S + BATCH*NQ*NQ;
constexpr size_t O_HB    = O_AO + MQ*DM;
constexpr size_t O_BOX   = O_HB + MQ*DM;             // 600*4
constexpr size_t G_TOTAL = O_BOX + MQ*4;

__device__ float g_buf[G_TOTAL];

// ---------------------------------------------------------------------------
// TF32 helpers
// ---------------------------------------------------------------------------
__device__ __forceinline__ uint32_t f2tf32(float x) {
  uint32_t r;
  asm("cvt.rna.tf32.f32 %0, %1;" : "=r"(r) : "f"(x));
  return r;
}
__device__ __forceinline__ void split_tf32(float x, uint32_t& hi, uint32_t& lo) {
  hi = f2tf32(x);
  lo = f2tf32(x - __uint_as_float(hi));
}
__device__ __forceinline__ void mma_tf32(float* c, const uint32_t* a, const uint32_t* b) {
  asm volatile(
    "mma.sync.aligned.m16n8k8.row.col.f32.tf32.tf32.f32 "
    "{%0,%1,%2,%3},{%4,%5,%6,%7},{%8,%9},{%0,%1,%2,%3};"
    : "+f"(c[0]), "+f"(c[1]), "+f"(c[2]), "+f"(c[3])
    : "r"(a[0]), "r"(a[1]), "r"(a[2]), "r"(a[3]), "r"(b[0]), "r"(b[1]));
}

// ---------------------------------------------------------------------------
// 3xTF32 GEMM, fragment-layout smem + double buffering.
// C[M,N] = A[M,K] @ Bw[N,K]^T. Block 128x64, 8 warps of 32x32, BK=16.
// Smem A: [tm(8)][tk(2)][lane(32)][reg(4)hi | reg(4)lo] with slot-XOR swizzle.
// Smem B: [np(4)][tk(2)][lane(32)][evenB0,evenB1,oddB0,oddB1 hi | same lo].
// EPI: 0=+bias, 1=+bias+relu, 2=+bias+res
// ---------------------------------------------------------------------------
template<int EPI>
__global__ __launch_bounds__(256, 2)
void gemm_tf32(const float* __restrict__ A, const float* __restrict__ Bw,
               const float* __restrict__ bias, const float* __restrict__ res,
               float* __restrict__ C, int M, int N, int K) {
  const int BM = 128, BN = 64, BK = 16;
  __shared__ uint32_t SA[2][4096];   // 16KB x2
  __shared__ uint32_t SB[2][2048];   // 8KB x2

  int tid = threadIdx.x;
  int bm = blockIdx.y * BM, bn = blockIdx.x * BN;
  int lane = tid & 31, warp = tid >> 5;
  int wm = (warp >> 1) * 32, wn = (warp & 1) * 32;
  int gid = lane >> 2, tig = lane & 3;

  float acc[2][4][4] = {};
  int Kpad = (K + BK - 1) / BK * BK;

  // fill assignments
  int am[2], ak[2];
  #pragma unroll
  for (int l = 0; l < 2; ++l) {
    int li = tid + l * 256;
    am[l] = li >> 2;            // 0..127
    ak[l] = (li & 3) * 4;       // 0,4,8,12
  }
  int bnr = tid >> 2;           // 0..63
  int bkr = (tid & 3) * 4;

  float4 pa[2], pb;

  auto loadA = [&](int k0, int l) -> float4 {
    float4 v = make_float4(0.f, 0.f, 0.f, 0.f);
    int gm = bm + am[l], gk = k0 + ak[l];
    if (gm < M) {
      if (gk + 3 < K) v = *reinterpret_cast<const float4*>(A + (size_t)gm * K + gk);
      else {
        float t[4] = {0.f, 0.f, 0.f, 0.f};
        #pragma unroll
        for (int e = 0; e < 4; ++e) if (gk + e < K) t[e] = A[(size_t)gm * K + gk + e];
        v = make_float4(t[0], t[1], t[2], t[3]);
      }
    }
    return v;
  };
  auto loadB = [&](int k0) -> float4 {
    float4 v = make_float4(0.f, 0.f, 0.f, 0.f);
    int gn = bn + bnr, gk = k0 + bkr;
    if (gn < N) {
      if (gk + 3 < K) v = *reinterpret_cast<const float4*>(Bw + (size_t)gn * K + gk);
      else {
        float t[4] = {0.f, 0.f, 0.f, 0.f};
        #pragma unroll
        for (int e = 0; e < 4; ++e) if (gk + e < K) t[e] = Bw[(size_t)gn * K + gk + e];
        v = make_float4(t[0], t[1], t[2], t[3]);
      }
    }
    return v;
  };

  auto storeTiles = [&](int buf) {
    #pragma unroll
    for (int l = 0; l < 2; ++l) {
      float v[4] = {pa[l].x, pa[l].y, pa[l].z, pa[l].w};
      int tm = am[l] >> 4, r = am[l] & 15;
      #pragma unroll
      for (int e = 0; e < 4; ++e) {
        int kl = ak[l] + e;
        int tk = kl >> 3, k8 = kl & 7;
        int lw = (r & 7) * 4 + (k8 & 3);
        int reg = (r >> 3) + ((k8 >> 2) << 1);
        uint32_t hi, lo; split_tf32(v[e], hi, lo);
        int s0 = (((tm * 2 + tk) * 32 + lw) * 2) ^ ((lw >> 2) & 7);
        SA[buf][s0 * 4 + reg]       = hi;
        SA[buf][(s0 ^ 1) * 4 + reg] = lo;
      }
    }
    {
      float v[4] = {pb.x, pb.y, pb.z, pb.w};
      int ntile = bnr >> 3, gidn = bnr & 7;
      int np = ntile >> 1, nodd = ntile & 1;
      #pragma unroll
      for (int e = 0; e < 4; ++e) {
        int kl = bkr + e;
        int tk = kl >> 3, k8 = kl & 7;
        int lw = gidn * 4 + (k8 & 3);
        int reg = k8 >> 2;
        int word = nodd * 2 + reg;
        uint32_t hi, lo; split_tf32(v[e], hi, lo);
        int s0 = (((np * 2 + tk) * 32 + lw) * 2) ^ ((lw >> 2) & 7);
        SB[buf][s0 * 4 + word]       = hi;
        SB[buf][(s0 ^ 1) * 4 + word] = lo;
      }
    }
  };

  // prologue: fill buffer 0, prefetch next
  pa[0] = loadA(0, 0); pa[1] = loadA(0, 1); pb = loadB(0);
  storeTiles(0);
  if (BK < Kpad) { pa[0] = loadA(BK, 0); pa[1] = loadA(BK, 1); pb = loadB(BK); }
  __syncthreads();

  int cur = 0;
  int xr = (lane >> 2) & 7;
  for (int k0 = 0; k0 < Kpad; k0 += BK) {
    if (k0 + BK < Kpad) {
      storeTiles(cur ^ 1);
      if (k0 + 2 * BK < Kpad) {
        pa[0] = loadA(k0 + 2 * BK, 0); pa[1] = loadA(k0 + 2 * BK, 1);
        pb = loadB(k0 + 2 * BK);
      }
    }
    #pragma unroll
    for (int ks = 0; ks < 2; ++ks) {
      uint32_t Ahf[2][4], Alf[2][4];
      #pragma unroll
      for (int i = 0; i < 2; ++i) {
        int tm = (wm >> 4) + i;
        int s0 = (((tm * 2 + ks) * 32 + lane) * 2) ^ xr;
        *reinterpret_cast<uint4*>(Ahf[i]) = *reinterpret_cast<const uint4*>(&SA[cur][s0 * 4]);
        *reinterpret_cast<uint4*>(Alf[i]) = *reinterpret_cast<const uint4*>(&SA[cur][(s0 ^ 1) * 4]);
      }
      uint32_t Bhf[2][4], Blf[2][4];
      #pragma unroll
      for (int jp = 0; jp < 2; ++jp) {
        int np = (wn >> 4) + jp;
        int s0 = (((np * 2 + ks) * 32 + lane) * 2) ^ xr;
        *reinterpret_cast<uint4*>(Bhf[jp]) = *reinterpret_cast<const uint4*>(&SB[cur][s0 * 4]);
        *reinterpret_cast<uint4*>(Blf[jp]) = *reinterpret_cast<const uint4*>(&SB[cur][(s0 ^ 1) * 4]);
      }
      #pragma unroll
      for (int i = 0; i < 2; ++i)
        #pragma unroll
        for (int jp = 0; jp < 2; ++jp)
          #pragma unroll
          for (int nodd = 0; nodd < 2; ++nodd) {
            int j = jp * 2 + nodd;
            uint32_t bh[2] = {Bhf[jp][nodd * 2], Bhf[jp][nodd * 2 + 1]};
            uint32_t bl[2] = {Blf[jp][nodd * 2], Blf[jp][nodd * 2 + 1]};
            mma_tf32(acc[i][j], Ahf[i], bh);
            mma_tf32(acc[i][j], Ahf[i], bl);
            mma_tf32(acc[i][j], Alf[i], bh);
          }
    }
    __syncthreads();
    cur ^= 1;
  }

  // epilogue
  #pragma unroll
  for (int i = 0; i < 2; ++i) {
    #pragma unroll
    for (int j = 0; j < 4; ++j) {
      int c0 = bn + wn + 8 * j + 2 * tig;
      #pragma unroll
      for (int half = 0; half < 2; ++half) {
        int gm = bm + wm + 16 * i + gid + 8 * half;
        if (gm >= M) continue;
        #pragma unroll
        for (int e = 0; e < 2; ++e) {
          int gn = c0 + e;
          if (gn >= N) continue;
          float v = acc[i][j][half * 2 + e] + (bias ? bias[gn] : 0.f);
          if (EPI == 1) v = fmaxf(v, 0.f);
          if (EPI == 2) v += res[(size_t)gm * N + gn];
          C[(size_t)gm * N + gn] = v;
        }
      }
    }
  }
}

// ---------------------------------------------------------------------------
// Stem weight combine
// ---------------------------------------------------------------------------
__global__ __launch_bounds__(256)
void k_wcomb(const float* __restrict__ w_tf, const float* __restrict__ w_in,
             const float* __restrict__ b_tf, const float* __restrict__ b_in,
             float* __restrict__ wcomb, float* __restrict__ bcomb) {
  int idx = blockIdx.x * 256 + threadIdx.x;
  if (idx < 256 * 512) {
    int dm = idx >> 9, k = idx & 511, i = k >> 2, t = k & 3;
    float s = 0.f;
    for (int c = 0; c < CIN; ++c) {
      const float* wt = w_tf + (c * CIN + i) * 3;
      float we = wt[1];
      if (t != 3) we += wt[0];
      if (t != 0) we += wt[2];
      s += w_in[dm * CIN + c] * we;
    }
    wcomb[idx] = 0.25f * s;
  }
  if (idx < 256) {
    float s = b_in[idx];
    for (int c = 0; c < CIN; ++c) s += w_in[idx * CIN + c] * b_tf[c];
    bcomb[idx] = s;
  }
}

__global__ __launch_bounds__(256)
void k_pos(float* __restrict__ py, float* __restrict__ px) {
  int idx = blockIdx.x * 256 + threadIdx.x;
  if (idx >= 2 * 64 * 128) return;
  int half = idx / (64 * 128);
  int r = idx - half * (64 * 128);
  int hw = r >> 7, c = r & 127;
  float dim_t = powf(10000.f, 2.f * (float)(c >> 2) / 64.f);
  float v = (float)(hw + 1) / (64.f + 1e-6f) * 2.f * 3.14159265358979323846f;
  float a = v / dim_t;
  float o = (c & 1) ? cosf(a) : sinf(a);
  if (half) px[r] = o; else py[r] = o;
}

// ---------------------------------------------------------------------------
// Stem GEMM (fp32, gathered A)
// ---------------------------------------------------------------------------
__global__ __launch_bounds__(256)
void k_stem(const float* __restrict__ feat, const float* __restrict__ wcomb,
            const float* __restrict__ bcomb, const float* __restrict__ py,
            const float* __restrict__ px, float* __restrict__ C) {
  const int BM = 128, BN = 64, BK = 16, K = 512, N = 256;
  __shared__ float As[BK][BM + 4];
  __shared__ float Bs[BK][BN + 4];
  int bm = blockIdx.y * BM, bn = blockIdx.x * BN;
  int tid = threadIdx.x;
  int tx = tid & 15, ty = tid >> 4;
  float acc[8][4] = {};
  for (int k0 = 0; k0 < K; k0 += BK) {
    #pragma unroll
    for (int l = 0; l < 8; ++l) {
      int e = tid + l * 256;
      int k = e >> 7, mm = e & 127;
      int gm = bm + mm, gk = k0 + k;
      int b = gm >> 12, hw = gm & 4095;
      int i = gk >> 2, t = gk & 3;
      As[k][mm] = feat[(size_t)(((b << 2) + t) * CIN + i) * HWSZ + hw];
    }
    {
      int m = tid >> 2, kq = (tid & 3) * 4;
      float4 v = *reinterpret_cast<const float4*>(wcomb + (size_t)(bn + m) * K + k0 + kq);
      Bs[kq + 0][m] = v.x; Bs[kq + 1][m] = v.y;
      Bs[kq + 2][m] = v.z; Bs[kq + 3][m] = v.w;
    }
    __syncthreads();
    #pragma unroll
    for (int kk = 0; kk < BK; ++kk) {
      float4 a0 = *reinterpret_cast<const float4*>(&As[kk][ty * 8]);
      float4 a1 = *reinterpret_cast<const float4*>(&As[kk][ty * 8 + 4]);
      float4 b0 = *reinterpret_cast<const float4*>(&Bs[kk][tx * 4]);
      float a[8] = {a0.x, a0.y, a0.z, a0.w, a1.x, a1.y, a1.z, a1.w};
      float b[4] = {b0.x, b0.y, b0.z, b0.w};
      #pragma unroll
      for (int i = 0; i < 8; ++i)
        #pragma unroll
        for (int j = 0; j < 4; ++j) acc[i][j] += a[i] * b[j];
    }
    __syncthreads();
  }
  #pragma unroll
  for (int i = 0; i < 8; ++i) {
    int gm = bm + ty * 8 + i;
    int hw = gm & 4095;
    int h = hw >> 6, w = hw & 63;
    #pragma unroll
    for (int j = 0; j < 4; ++j) {
      int gn = bn + tx * 4 + j;
      float pos = (gn < 128) ? py[h * 128 + gn] : px[w * 128 + gn - 128];
      C[(size_t)gm * N + gn] = acc[i][j] + bcomb[gn] + pos;
    }
  }
}

// im2col for 3x3 pad-1 conv on channel-last input
__global__ __launch_bounds__(256)
void k_im2col(const float* __restrict__ y, float* __restrict__ col) {
  int m = blockIdx.x;
  int b = m >> 12, hw = m & 4095;
  int h = hw >> 6, w = hw & 63;
  int i = threadIdx.x;
  float* out = col + (size_t)m * KP1 + i * 9;
  #pragma unroll
  for (int ky = 0; ky < 3; ++ky)
    #pragma unroll
    for (int kx = 0; kx < 3; ++kx) {
      int hh = h + ky - 1, ww = w + kx - 1;
      float v = 0.f;
      if (hh >= 0 && hh < 64 && ww >= 0 && ww < 64)
        v = y[((size_t)(b << 12) + (hh << 6) + ww) * DM + i];
      out[ky * 3 + kx] = v;
    }
}

__global__ __launch_bounds__(256)
void k_qinit(const float* __restrict__ q_embed, const float* __restrict__ q_pos,
             const float* __restrict__ boxes0, float* __restrict__ queries,
             float* __restrict__ boxes) {
  int m = blockIdx.x;
  int q = m % NQ;
  int d = threadIdx.x;
  queries[m * DM + d] = q_embed[q * DM + d] + q_pos[q * DM + d];
  if (d < 4) boxes[m * 4 + d] = boxes0[m * 4 + d];
}

__global__ __launch_bounds__(256)
void k_refpts(const float* __restrict__ h1, const float* __restrict__ boxes,
              const float* __restrict__ w_r2, const float* __restrict__ b_r2,
              float* __restrict__ ref) {
  int m = blockIdx.x;
  int g = threadIdx.x >> 4;
  int lane16 = threadIdx.x & 15;
  float s = 0.f;
  for (int d = lane16; d < DM; d += 16)
    s += h1[m * DM + d] * w_r2[g * DM + d];
  #pragma unroll
  for (int off = 8; off > 0; off >>= 1)
    s += __shfl_down_sync(0xffffffffu, s, off, 16);
  __shared__ float ro_s[16];
  if (lane16 == 0) ro_s[g] = tanhf(s + b_r2[g]) * 0.5f;
  __syncthreads();
  if (threadIdx.x < 16) {
    int p = threadIdx.x >> 1, j = threadIdx.x & 1;
    float v = boxes[m * 4 + j] + ro_s[p * 2 + j];
    ref[(m * NP + p) * 2 + j] = fminf(fmaxf(v, 0.f), 1.f);
  }
}

__global__ __launch_bounds__(256)
void k_sample(const float* __restrict__ f0, const float* __restrict__ ref,
              float* __restrict__ flat) {
  int blk = blockIdx.x;
  int kk = blk % 9;
  int rest = blk / 9;
  int p = rest & 7, m = rest >> 3;
  int b = (m >= NQ) ? 1 : 0;
  float rx = ref[(m * NP + p) * 2 + 0];
  float ry = ref[(m * NP + p) * 2 + 1];
  float oy = (float)(kk / 3 - 1), ox = (float)(kk % 3 - 1);
  float x = fminf(fmaxf((rx + ox * (1.f / 64.f)) * 63.f, 0.f), 63.f);
  float y = fminf(fmaxf((ry + oy * (1.f / 64.f)) * 63.f, 0.f), 63.f);
  float x0 = floorf(x), y0 = floorf(y);
  float wx = x - x0, wy = y - y0;
  int x0i = (int)x0, y0i = (int)y0;
  int x1i = min(x0i + 1, 63), y1i = min(y0i + 1, 63);
  int c = threadIdx.x;
  const float* f = f0 + (size_t)b * HWSZ * DM;
  float v00 = f[((y0i << 6) + x0i) * DM + c];
  float v01 = f[((y0i << 6) + x1i) * DM + c];
  float v10 = f[((y1i << 6) + x0i) * DM + c];
  float v11 = f[((y1i << 6) + x1i) * DM + c];
  float v = v00 * (1.f - wx) * (1.f - wy) + v01 * wx * (1.f - wy)
          + v10 * (1.f - wx) * wy + v11 * wx * wy;
  flat[(size_t)rest * KP1 + kk * DM + c] = v;
}

__global__ __launch_bounds__(256)
void k_mean(const float* __restrict__ pv, float* __restrict__ kvpre) {
  int m = blockIdx.x, d = threadIdx.x;
  float s = 0.f;
  #pragma unroll
  for (int p = 0; p < NP; ++p) s += pv[(size_t)(m * NP + p) * DM + d];
  kvpre[m * DM + d] = s * (1.f / NP);
}

__global__ __launch_bounds__(256)
void k_kvT(const float* __restrict__ kv, float* __restrict__ kvT) {
  int m = blockIdx.x;
  int b = (m >= NQ) ? 1 : 0;
  int k = m - b * NQ;
  int d = threadIdx.x;
  kvT[((size_t)b * DM + d) * NQ + k] = kv[(size_t)m * DM + d];
}

__global__ __launch_bounds__(512)
void k_softmax(float* __restrict__ S) {
  int m = blockIdx.x;
  int b = (m >= NQ) ? 1 : 0;
  float* row = S + (size_t)b * NQ * NQ + (size_t)(m - b * NQ) * NQ;
  int t = threadIdx.x;
  __shared__ float red[512];
  float v = (t < NQ) ? row[t] * 0.0625f : -1e30f;
  red[t] = v; __syncthreads();
  for (int s = 256; s > 0; s >>= 1) { if (t < s) red[t] = fmaxf(red[t], red[t + s]); __syncthreads(); }
  float mx = red[0]; __syncthreads();
  float e = (t < NQ) ? expf(v - mx) : 0.f;
  red[t] = e; __syncthreads();
  for (int s = 256; s > 0; s >>= 1) { if (t < s) red[t] += red[t + s]; __syncthreads(); }
  float inv = 1.f / red[0];
  if (t < NQ) row[t] = e * inv;
}

__global__ __launch_bounds__(128)
void k_box(const float* __restrict__ hb, const float* __restrict__ w_b2,
           const float* __restrict__ b_b2, float* __restrict__ boxes) {
  int m = blockIdx.x;
  int wj = threadIdx.x >> 5, lane = threadIdx.x & 31;
  float s = 0.f;
  for (int d = lane; d < DM; d += 32) s += hb[m * DM + d] * w_b2[wj * DM + d];
  #pragma unroll
  for (int off = 16; off > 0; off >>= 1) s += __shfl_down_sync(0xffffffffu, s, off);
  if (lane == 0) {
    float delta = 1.f / (1.f + expf(-(s + b_b2[wj])));
    float nb = boxes[m * 4 + wj] + 0.1f * tanhf(delta - 0.5f);
    boxes[m * 4 + wj] = fminf(fmaxf(nb, 0.f), 1.f);
  }
}

__global__ __launch_bounds__(256)
void k_logits(const float* __restrict__ queries, const float* __restrict__ w_cls,
              const float* __restrict__ b_cls, float* __restrict__ out) {
  int m = blockIdx.x, t = threadIdx.x;
  __shared__ float red[256];
  red[t] = queries[m * DM + t] * w_cls[t];
  __syncthreads();
  for (int s = 128; s > 0; s >>= 1) { if (t < s) red[t] += red[t + s]; __syncthreads(); }
  if (t == 0) out[m] = red[0] + b_cls[0];
}

__global__ __launch_bounds__(256)
void k_copyboxes(const float* __restrict__ boxes, float* __restrict__ out) {
  int i = blockIdx.x * 256 + threadIdx.x;
  if (i < MQ * 4) out[MQ + i] = boxes[i];
}

// ---------------------------------------------------------------------------
static inline dim3 ggrid(int M, int N) { return dim3((N + 63) / 64, (M + 127) / 128); }

extern "C" void kernel_launch(void* const* d_in, const int* in_sizes, int n_in,
                              void* d_out, int out_size) {
  const float* feat   = (const float*)d_in[0];
  const float* boxes0 = (const float*)d_in[1];
  const float* w_tf   = (const float*)d_in[2];
  const float* b_tf   = (const float*)d_in[3];
  const float* w_in   = (const float*)d_in[4];
  const float* b_in   = (const float*)d_in[5];
  const float* w_lat  = (const float*)d_in[6];
  const float* b_lat  = (const float*)d_in[7];
  const float* w_sm   = (const float*)d_in[8];
  const float* b_sm   = (const float*)d_in[9];
  const float* q_embed= (const float*)d_in[10];
  const float* q_pos  = (const float*)d_in[11];
  const float* Wq     = (const float*)d_in[12];
  const float* bq     = (const float*)d_in[13];
  const float* Wo     = (const float*)d_in[14];
  const float* bo     = (const float*)d_in[15];
  const float* Wp1    = (const float*)d_in[16];
  const float* bp1    = (const float*)d_in[17];
  const float* Wp2    = (const float*)d_in[18];
  const float* bp2    = (const float*)d_in[19];
  const float* w_r1   = (const float*)d_in[20];
  const float* b_r1   = (const float*)d_in[21];
  const float* w_r2   = (const float*)d_in[22];
  const float* b_r2   = (const float*)d_in[23];
  const float* w_b1   = (const float*)d_in[24];
  const float* b_b1   = (const float*)d_in[25];
  const float* w_b2   = (const float*)d_in[26];
  const float* b_b2   = (const float*)d_in[27];
  const float* w_cls  = (const float*)d_in[28];
  const float* b_cls  = (const float*)d_in[29];
  float* out = (float*)d_out;

  float* base = nullptr;
  cudaGetSymbolAddress((void**)&base, g_buf);
  float* p_wcomb = base + O_WCOMB;
  float* p_bcomb = base + O_BCOMB;
  float* p_py    = base + O_PY;
  float* p_px    = base + O_PX;
  float* p_x     = base + O_X;
  float* p_lat   = base + O_LAT;
  float* p_col   = base + O_COL;
  float* p_f0    = base + O_F0;
  float* p_q     = base + O_Q;
  float* p_h1    = base + O_H1;
  float* p_ref   = base + O_REF;
  float* p_flat  = base + O_FLAT;
  float* p_pv    = base + O_PV;
  float* p_kvp   = base + O_KVP;
  float* p_kv    = base + O_KV;
  float* p_qp    = base + O_QP;
  float* p_kvT   = base + O_KVT;
  float* p_S     = base + O_S;
  float* p_ao    = base + O_AO;
  float* p_hb    = base + O_HB;
  float* p_box   = base + O_BOX;

  // ---- stem (conv3d + mean_T + in-proj fused) + pos ----
  k_wcomb<<<(256 * 512 + 255) / 256, 256>>>(w_tf, w_in, b_tf, b_in, p_wcomb, p_bcomb);
  k_pos<<<(2 * 64 * 128 + 255) / 256, 256>>>(p_py, p_px);
  k_stem<<<ggrid(MROWS, DM), 256>>>(feat, p_wcomb, p_bcomb, p_py, p_px, p_x);

  // ---- scale-1 feature only (scales 2,4 dead in reference) ----
  gemm_tf32<0><<<ggrid(MROWS, DM), 256>>>(p_x, w_lat, b_lat, nullptr, p_lat, MROWS, DM, DM);
  k_im2col<<<MROWS, 256>>>(p_lat, p_col);
  gemm_tf32<0><<<ggrid(MROWS, DM), 256>>>(p_col, w_sm, b_sm, nullptr, p_f0, MROWS, DM, KP1);

  // ---- decoder init ----
  k_qinit<<<MQ, 256>>>(q_embed, q_pos, boxes0, p_q, p_box);

  for (int l = 0; l < NLAY; ++l) {
    const float* Wq_l  = Wq  + (size_t)l * DM * DM;
    const float* bq_l  = bq  + (size_t)l * DM;
    const float* Wo_l  = Wo  + (size_t)l * DM * DM;
    const float* bo_l  = bo  + (size_t)l * DM;
    const float* Wp1_l = Wp1 + (size_t)l * DM * KP1;
    const float* bp1_l = bp1 + (size_t)l * DM;
    const float* Wp2_l = Wp2 + (size_t)l * DM * DM;
    const float* bp2_l = bp2 + (size_t)l * DM;

    gemm_tf32<1><<<ggrid(MQ, DM), 256>>>(p_q, w_r1, b_r1, nullptr, p_h1, MQ, DM, DM);
    k_refpts<<<MQ, 256>>>(p_h1, p_box, w_r2, b_r2, p_ref);

    k_sample<<<MQ * NP * 9, 256>>>(p_f0, p_ref, p_flat);

    gemm_tf32<1><<<ggrid(MS, DM), 256>>>(p_flat, Wp1_l, bp1_l, nullptr, p_pv, MS, DM, KP1);
    k_mean<<<MQ, 256>>>(p_pv, p_kvp);
    gemm_tf32<0><<<ggrid(MQ, DM), 256>>>(p_kvp, Wp2_l, bp2_l, nullptr, p_kv, MQ, DM, DM);

    gemm_tf32<0><<<ggrid(MQ, DM), 256>>>(p_q, Wq_l, bq_l, nullptr, p_qp, MQ, DM, DM);
    k_kvT<<<MQ, 256>>>(p_kv, p_kvT);
    for (int b = 0; b < BATCH; ++b)
      gemm_tf32<0><<<ggrid(NQ, NQ), 256>>>(p_qp + (size_t)b * NQ * DM,
                                           p_kv + (size_t)b * NQ * DM,
                                           nullptr, nullptr,
                                           p_S + (size_t)b * NQ * NQ, NQ, NQ, DM);
    k_softmax<<<MQ, 512>>>(p_S);
    for (int b = 0; b < BATCH; ++b)
      gemm_tf32<0><<<ggrid(NQ, DM), 256>>>(p_S + (size_t)b * NQ * NQ,
                                           p_kvT + (size_t)b * DM * NQ,
                                           nullptr, nullptr,
                                           p_ao + (size_t)b * NQ * DM, NQ, DM, NQ);
    gemm_tf32<2><<<ggrid(MQ, DM), 256>>>(p_ao, Wo_l, bo_l, p_q, p_q, MQ, DM, DM);

    gemm_tf32<1><<<ggrid(MQ, DM), 256>>>(p_q, w_b1, b_b1, nullptr, p_hb, MQ, DM, DM);
    k_box<<<MQ, 128>>>(p_hb, w_b2, b_b2, p_box);
  }

  k_logits<<<MQ, 256>>>(p_q, w_cls, b_cls, out);
  k_copyboxes<<<(MQ * 4 + 255) / 256, 256>>>(p_box, out);
}

// round 5
// speedup vs baseline: 1.3710x; 1.0079x over previous
#include <cuda_runtime.h>
#include <math.h>
#include <stdint.h>

// ---------------------------------------------------------------------------
// Problem constants
// ---------------------------------------------------------------------------
#define HH 64
#define WW 64
#define HWSZ 4096
#define CIN 128
#define TT 4
#define DM 256
#define NQ 300
#define NP 8
#define NLAY 6
#define BATCH 2
#define MROWS (BATCH*HWSZ)      // 8192 spatial rows
#define MQ (BATCH*NQ)           // 600 query rows
#define MS (MQ*NP)              // 4800 sample rows
#define KP1 2304                // 3*3*256

// ---------------------------------------------------------------------------
// Scratch
// ---------------------------------------------------------------------------
constexpr size_t O_WCOMB = 0;                        // 256*512
constexpr size_t O_BCOMB = O_WCOMB + 256*512;        // 256
constexpr size_t O_PY    = O_BCOMB + 256;            // 64*128
constexpr size_t O_PX    = O_PY + 64*128;            // 64*128
constexpr size_t O_WSMP  = O_PX + 64*128;            // 256*2304 permuted w_sm
constexpr size_t O_X     = O_WSMP + (size_t)DM*KP1;  // 8192*256
constexpr size_t O_LAT   = O_X + (size_t)MROWS*DM;   // 8192*256
constexpr size_t O_F0    = O_LAT + (size_t)MROWS*DM; // 8192*256
constexpr size_t O_Q     = O_F0 + (size_t)MROWS*DM;  // 600*256
constexpr size_t O_H1    = O_Q + MQ*DM;
constexpr size_t O_REF   = O_H1 + MQ*DM;             // 600*8*2
constexpr size_t O_FLAT  = O_REF + MQ*NP*2;          // 4800*2304
constexpr size_t O_PV    = O_FLAT + (size_t)MS*KP1;  // 4800*256
constexpr size_t O_KVP   = O_PV + (size_t)MS*DM;
constexpr size_t O_KV    = O_KVP + MQ*DM;
constexpr size_t O_QP    = O_KV + MQ*DM;
constexpr size_t O_KVT   = O_QP + MQ*DM;             // 2*256*300
constexpr size_t O_S     = O_KVT + MQ*DM;            // 2*300*300
constexpr size_t O_AO    = O_S + BATCH*NQ*NQ;
constexpr size_t O_HB    = O_AO + MQ*DM;
constexpr size_t O_BOX   = O_HB + MQ*DM;             // 600*4
constexpr size_t G_TOTAL = O_BOX + MQ*4;

__device__ float g_buf[G_TOTAL];

// ---------------------------------------------------------------------------
// TF32 helpers
// ---------------------------------------------------------------------------
__device__ __forceinline__ uint32_t f2tf32(float x) {
  uint32_t r;
  asm("cvt.rna.tf32.f32 %0, %1;" : "=r"(r) : "f"(x));
  return r;
}
__device__ __forceinline__ void split_tf32(float x, uint32_t& hi, uint32_t& lo) {
  hi = f2tf32(x);
  lo = f2tf32(x - __uint_as_float(hi));
}
__device__ __forceinline__ void mma_tf32(float* c, const uint32_t* a, const uint32_t* b) {
  asm volatile(
    "mma.sync.aligned.m16n8k8.row.col.f32.tf32.tf32.f32 "
    "{%0,%1,%2,%3},{%4,%5,%6,%7},{%8,%9},{%0,%1,%2,%3};"
    : "+f"(c[0]), "+f"(c[1]), "+f"(c[2]), "+f"(c[3])
    : "r"(a[0]), "r"(a[1]), "r"(a[2]), "r"(a[3]), "r"(b[0]), "r"(b[1]));
}

// ---------------------------------------------------------------------------
// 3xTF32 GEMM v2. Block 128x64, 8 warps of 32x32, BK=32, double-buffered
// dynamic smem (96KB), fragment-layout + XOR swizzle.
// GATHER=1: A gathered as im2col ([ky][kx][c] K-order) of (b,64,64,256)
//           channel-last map; pair with [o][ky][kx][c]-permuted weights.
// EPI: 0=+bias, 1=+bias+relu, 2=+bias+res. Batched via blockIdx.z strides.
// ---------------------------------------------------------------------------
template<int EPI, int GATHER>
__global__ __launch_bounds__(256, 2)
void gemm_tf32(const float* __restrict__ A, const float* __restrict__ Bw,
               const float* __restrict__ bias, const float* __restrict__ res,
               float* __restrict__ C, int M, int N, int K,
               long long sA, long long sB, long long sC) {
  const int BM = 128, BN = 64, BK = 32;
  extern __shared__ uint32_t smem[];
  uint32_t* SAb = smem;            // 2 x 8192 words
  uint32_t* SBb = smem + 16384;    // 2 x 4096 words

  A  += blockIdx.z * sA;
  Bw += blockIdx.z * sB;
  C  += blockIdx.z * sC;

  int tid = threadIdx.x;
  int bm = blockIdx.y * BM, bn = blockIdx.x * BN;
  int lane = tid & 31, warp = tid >> 5;
  int wm = (warp >> 1) * 32, wn = (warp & 1) * 32;
  int gid = lane >> 2, tig = lane & 3;
  int xr = (lane >> 2) & 7;

  float acc[2][4][4] = {};
  int Kpad = (K + BK - 1) / BK * BK;

  int am4[4], ak4[4], bn2[2], bk2[2];
  #pragma unroll
  for (int l = 0; l < 4; ++l) {
    int li = tid + l * 256;
    am4[l] = li >> 3;
    ak4[l] = (li & 7) * 4;
  }
  #pragma unroll
  for (int l = 0; l < 2; ++l) {
    int li = tid + l * 256;
    bn2[l] = li >> 3;
    bk2[l] = (li & 7) * 4;
  }

  float4 pa[4], pb[2];

  auto loadA = [&](int k0, int l) -> float4 {
    float4 v = make_float4(0.f, 0.f, 0.f, 0.f);
    int gm = bm + am4[l], gk = k0 + ak4[l];
    if (GATHER) {
      // K-order [ky][kx][c]: gk = ky*768 + kx*256 + c (c 4-aligned here)
      if (gm < M && gk < K) {
        int ky = gk / 768, rem = gk - ky * 768;
        int kx = rem >> 8, c = rem & 255;
        int b = gm >> 12, hw = gm & 4095, h = hw >> 6, w = hw & 63;
        int hh = h + ky - 1, ww = w + kx - 1;
        if (hh >= 0 && hh < 64 && ww >= 0 && ww < 64)
          v = *reinterpret_cast<const float4*>(A + ((size_t)(b << 12) + (hh << 6) + ww) * 256 + c);
      }
    } else {
      if (gm < M) {
        if (gk + 3 < K) v = *reinterpret_cast<const float4*>(A + (size_t)gm * K + gk);
        else {
          float t[4] = {0.f, 0.f, 0.f, 0.f};
          #pragma unroll
          for (int e = 0; e < 4; ++e) if (gk + e < K) t[e] = A[(size_t)gm * K + gk + e];
          v = make_float4(t[0], t[1], t[2], t[3]);
        }
      }
    }
    return v;
  };
  auto loadB = [&](int k0, int l) -> float4 {
    float4 v = make_float4(0.f, 0.f, 0.f, 0.f);
    int gn = bn + bn2[l], gk = k0 + bk2[l];
    if (gn < N) {
      if (gk + 3 < K) v = *reinterpret_cast<const float4*>(Bw + (size_t)gn * K + gk);
      else {
        float t[4] = {0.f, 0.f, 0.f, 0.f};
        #pragma unroll
        for (int e = 0; e < 4; ++e) if (gk + e < K) t[e] = Bw[(size_t)gn * K + gk + e];
        v = make_float4(t[0], t[1], t[2], t[3]);
      }
    }
    return v;
  };
  auto prefetch = [&](int k0) {
    #pragma unroll
    for (int l = 0; l < 4; ++l) pa[l] = loadA(k0, l);
    #pragma unroll
    for (int l = 0; l < 2; ++l) pb[l] = loadB(k0, l);
  };

  auto storeTiles = [&](int buf) {
    uint32_t* SA = SAb + buf * 8192;
    uint32_t* SB = SBb + buf * 4096;
    #pragma unroll
    for (int l = 0; l < 4; ++l) {
      float v[4] = {pa[l].x, pa[l].y, pa[l].z, pa[l].w};
      int tm = am4[l] >> 4, r = am4[l] & 15;
      #pragma unroll
      for (int e = 0; e < 4; ++e) {
        int kl = ak4[l] + e;
        int tk = kl >> 3, k8 = kl & 7;
        int lw = (r & 7) * 4 + (k8 & 3);
        int reg = (r >> 3) + ((k8 >> 2) << 1);
        uint32_t hi, lo; split_tf32(v[e], hi, lo);
        int s0 = (((tm * 4 + tk) * 32 + lw) * 2) ^ ((lw >> 2) & 7);
        SA[s0 * 4 + reg]       = hi;
        SA[(s0 ^ 1) * 4 + reg] = lo;
      }
    }
    #pragma unroll
    for (int l = 0; l < 2; ++l) {
      float v[4] = {pb[l].x, pb[l].y, pb[l].z, pb[l].w};
      int ntile = bn2[l] >> 3, gidn = bn2[l] & 7;
      int np = ntile >> 1, nodd = ntile & 1;
      #pragma unroll
      for (int e = 0; e < 4; ++e) {
        int kl = bk2[l] + e;
        int tk = kl >> 3, k8 = kl & 7;
        int lw = gidn * 4 + (k8 & 3);
        int reg = k8 >> 2;
        int word = nodd * 2 + reg;
        uint32_t hi, lo; split_tf32(v[e], hi, lo);
        int s0 = (((np * 4 + tk) * 32 + lw) * 2) ^ ((lw >> 2) & 7);
        SB[s0 * 4 + word]       = hi;
        SB[(s0 ^ 1) * 4 + word] = lo;
      }
    }
  };

  prefetch(0);
  storeTiles(0);
  if (BK < Kpad) prefetch(BK);
  __syncthreads();

  int cur = 0;
  for (int k0 = 0; k0 < Kpad; k0 += BK) {
    if (k0 + BK < Kpad) {
      storeTiles(cur ^ 1);
      if (k0 + 2 * BK < Kpad) prefetch(k0 + 2 * BK);
    }
    const uint32_t* SA = SAb + cur * 8192;
    const uint32_t* SB = SBb + cur * 4096;
    #pragma unroll
    for (int tk = 0; tk < 4; ++tk) {
      uint32_t Ahf[2][4], Alf[2][4];
      #pragma unroll
      for (int i = 0; i < 2; ++i) {
        int tm = (wm >> 4) + i;
        int s0 = (((tm * 4 + tk) * 32 + lane) * 2) ^ xr;
        *reinterpret_cast<uint4*>(Ahf[i]) = *reinterpret_cast<const uint4*>(&SA[s0 * 4]);
        *reinterpret_cast<uint4*>(Alf[i]) = *reinterpret_cast<const uint4*>(&SA[(s0 ^ 1) * 4]);
      }
      uint32_t Bhf[2][4], Blf[2][4];
      #pragma unroll
      for (int jp = 0; jp < 2; ++jp) {
        int np = (wn >> 4) + jp;
        int s0 = (((np * 4 + tk) * 32 + lane) * 2) ^ xr;
        *reinterpret_cast<uint4*>(Bhf[jp]) = *reinterpret_cast<const uint4*>(&SB[s0 * 4]);
        *reinterpret_cast<uint4*>(Blf[jp]) = *reinterpret_cast<const uint4*>(&SB[(s0 ^ 1) * 4]);
      }
      #pragma unroll
      for (int i = 0; i < 2; ++i)
        #pragma unroll
        for (int jp = 0; jp < 2; ++jp)
          #pragma unroll
          for (int nodd = 0; nodd < 2; ++nodd) {
            int j = jp * 2 + nodd;
            uint32_t bh[2] = {Bhf[jp][nodd * 2], Bhf[jp][nodd * 2 + 1]};
            uint32_t bl[2] = {Blf[jp][nodd * 2], Blf[jp][nodd * 2 + 1]};
            mma_tf32(acc[i][j], Ahf[i], bh);
            mma_tf32(acc[i][j], Ahf[i], bl);
            mma_tf32(acc[i][j], Alf[i], bh);
          }
    }
    __syncthreads();
    cur ^= 1;
  }

  #pragma unroll
  for (int i = 0; i < 2; ++i) {
    #pragma unroll
    for (int j = 0; j < 4; ++j) {
      int c0 = bn + wn + 8 * j + 2 * tig;
      #pragma unroll
      for (int half = 0; half < 2; ++half) {
        int gm = bm + wm + 16 * i + gid + 8 * half;
        if (gm >= M) continue;
        #pragma unroll
        for (int e = 0; e < 2; ++e) {
          int gn = c0 + e;
          if (gn >= N) continue;
          float v = acc[i][j][half * 2 + e] + (bias ? bias[gn] : 0.f);
          if (EPI == 1) v = fmaxf(v, 0.f);
          if (EPI == 2) v += res[(size_t)gm * N + gn];
          C[(size_t)gm * N + gn] = v;
        }
      }
    }
  }
}

// ---------------------------------------------------------------------------
// Permute w_sm [o][c][ky][kx] -> [o][ky][kx][c]  (match GATHER K-order)
// ---------------------------------------------------------------------------
__global__ __launch_bounds__(256)
void k_wsmperm(const float* __restrict__ w_sm, float* __restrict__ out) {
  int idx = blockIdx.x * 256 + threadIdx.x;
  if (idx >= DM * KP1) return;
  int o = idx / KP1, r = idx - o * KP1;
  int ky = r / 768, rem = r - ky * 768;
  int kx = rem >> 8, c = rem & 255;
  out[idx] = w_sm[(size_t)o * KP1 + c * 9 + ky * 3 + kx];
}

// ---------------------------------------------------------------------------
// Stem weight combine
// ---------------------------------------------------------------------------
__global__ __launch_bounds__(256)
void k_wcomb(const float* __restrict__ w_tf, const float* __restrict__ w_in,
             const float* __restrict__ b_tf, const float* __restrict__ b_in,
             float* __restrict__ wcomb, float* __restrict__ bcomb) {
  int idx = blockIdx.x * 256 + threadIdx.x;
  if (idx < 256 * 512) {
    int dm = idx >> 9, k = idx & 511, i = k >> 2, t = k & 3;
    float s = 0.f;
    for (int c = 0; c < CIN; ++c) {
      const float* wt = w_tf + (c * CIN + i) * 3;
      float we = wt[1];
      if (t != 3) we += wt[0];
      if (t != 0) we += wt[2];
      s += w_in[dm * CIN + c] * we;
    }
    wcomb[idx] = 0.25f * s;
  }
  if (idx < 256) {
    float s = b_in[idx];
    for (int c = 0; c < CIN; ++c) s += w_in[idx * CIN + c] * b_tf[c];
    bcomb[idx] = s;
  }
}

__global__ __launch_bounds__(256)
void k_pos(float* __restrict__ py, float* __restrict__ px) {
  int idx = blockIdx.x * 256 + threadIdx.x;
  if (idx >= 2 * 64 * 128) return;
  int half = idx / (64 * 128);
  int r = idx - half * (64 * 128);
  int hw = r >> 7, c = r & 127;
  float dim_t = powf(10000.f, 2.f * (float)(c >> 2) / 64.f);
  float v = (float)(hw + 1) / (64.f + 1e-6f) * 2.f * 3.14159265358979323846f;
  float a = v / dim_t;
  float o = (c & 1) ? cosf(a) : sinf(a);
  if (half) px[r] = o; else py[r] = o;
}

// ---------------------------------------------------------------------------
// Stem GEMM (fp32, gathered A)
// ---------------------------------------------------------------------------
__global__ __launch_bounds__(256)
void k_stem(const float* __restrict__ feat, const float* __restrict__ wcomb,
            const float* __restrict__ bcomb, const float* __restrict__ py,
            const float* __restrict__ px, float* __restrict__ C) {
  const int BM = 128, BN = 64, BK = 16, K = 512, N = 256;
  __shared__ float As[BK][BM + 4];
  __shared__ float Bs[BK][BN + 4];
  int bm = blockIdx.y * BM, bn = blockIdx.x * BN;
  int tid = threadIdx.x;
  int tx = tid & 15, ty = tid >> 4;
  float acc[8][4] = {};
  for (int k0 = 0; k0 < K; k0 += BK) {
    #pragma unroll
    for (int l = 0; l < 8; ++l) {
      int e = tid + l * 256;
      int k = e >> 7, mm = e & 127;
      int gm = bm + mm, gk = k0 + k;
      int b = gm >> 12, hw = gm & 4095;
      int i = gk >> 2, t = gk & 3;
      As[k][mm] = feat[(size_t)(((b << 2) + t) * CIN + i) * HWSZ + hw];
    }
    {
      int m = tid >> 2, kq = (tid & 3) * 4;
      float4 v = *reinterpret_cast<const float4*>(wcomb + (size_t)(bn + m) * K + k0 + kq);
      Bs[kq + 0][m] = v.x; Bs[kq + 1][m] = v.y;
      Bs[kq + 2][m] = v.z; Bs[kq + 3][m] = v.w;
    }
    __syncthreads();
    #pragma unroll
    for (int kk = 0; kk < BK; ++kk) {
      float4 a0 = *reinterpret_cast<const float4*>(&As[kk][ty * 8]);
      float4 a1 = *reinterpret_cast<const float4*>(&As[kk][ty * 8 + 4]);
      float4 b0 = *reinterpret_cast<const float4*>(&Bs[kk][tx * 4]);
      float a[8] = {a0.x, a0.y, a0.z, a0.w, a1.x, a1.y, a1.z, a1.w};
      float b[4] = {b0.x, b0.y, b0.z, b0.w};
      #pragma unroll
      for (int i = 0; i < 8; ++i)
        #pragma unroll
        for (int j = 0; j < 4; ++j) acc[i][j] += a[i] * b[j];
    }
    __syncthreads();
  }
  #pragma unroll
  for (int i = 0; i < 8; ++i) {
    int gm = bm + ty * 8 + i;
    int hw = gm & 4095;
    int h = hw >> 6, w = hw & 63;
    #pragma unroll
    for (int j = 0; j < 4; ++j) {
      int gn = bn + tx * 4 + j;
      float pos = (gn < 128) ? py[h * 128 + gn] : px[w * 128 + gn - 128];
      C[(size_t)gm * N + gn] = acc[i][j] + bcomb[gn] + pos;
    }
  }
}

__global__ __launch_bounds__(256)
void k_qinit(const float* __restrict__ q_embed, const float* __restrict__ q_pos,
             const float* __restrict__ boxes0, float* __restrict__ queries,
             float* __restrict__ boxes) {
  int m = blockIdx.x;
  int q = m % NQ;
  int d = threadIdx.x;
  queries[m * DM + d] = q_embed[q * DM + d] + q_pos[q * DM + d];
  if (d < 4) boxes[m * 4 + d] = boxes0[m * 4 + d];
}

__global__ __launch_bounds__(256)
void k_refpts(const float* __restrict__ h1, const float* __restrict__ boxes,
              const float* __restrict__ w_r2, const float* __restrict__ b_r2,
              float* __restrict__ ref) {
  int m = blockIdx.x;
  int g = threadIdx.x >> 4;
  int lane16 = threadIdx.x & 15;
  float s = 0.f;
  for (int d = lane16; d < DM; d += 16)
    s += h1[m * DM + d] * w_r2[g * DM + d];
  #pragma unroll
  for (int off = 8; off > 0; off >>= 1)
    s += __shfl_down_sync(0xffffffffu, s, off, 16);
  __shared__ float ro_s[16];
  if (lane16 == 0) ro_s[g] = tanhf(s + b_r2[g]) * 0.5f;
  __syncthreads();
  if (threadIdx.x < 16) {
    int p = threadIdx.x >> 1, j = threadIdx.x & 1;
    float v = boxes[m * 4 + j] + ro_s[p * 2 + j];
    ref[(m * NP + p) * 2 + j] = fminf(fmaxf(v, 0.f), 1.f);
  }
}

__global__ __launch_bounds__(256)
void k_sample(const float* __restrict__ f0, const float* __restrict__ ref,
              float* __restrict__ flat) {
  int blk = blockIdx.x;
  int kk = blk % 9;
  int rest = blk / 9;
  int p = rest & 7, m = rest >> 3;
  int b = (m >= NQ) ? 1 : 0;
  float rx = ref[(m * NP + p) * 2 + 0];
  float ry = ref[(m * NP + p) * 2 + 1];
  float oy = (float)(kk / 3 - 1), ox = (float)(kk % 3 - 1);
  float x = fminf(fmaxf((rx + ox * (1.f / 64.f)) * 63.f, 0.f), 63.f);
  float y = fminf(fmaxf((ry + oy * (1.f / 64.f)) * 63.f, 0.f), 63.f);
  float x0 = floorf(x), y0 = floorf(y);
  float wx = x - x0, wy = y - y0;
  int x0i = (int)x0, y0i = (int)y0;
  int x1i = min(x0i + 1, 63), y1i = min(y0i + 1, 63);
  int c = threadIdx.x;
  const float* f = f0 + (size_t)b * HWSZ * DM;
  float v00 = f[((y0i << 6) + x0i) * DM + c];
  float v01 = f[((y0i << 6) + x1i) * DM + c];
  float v10 = f[((y1i << 6) + x0i) * DM + c];
  float v11 = f[((y1i << 6) + x1i) * DM + c];
  float v = v00 * (1.f - wx) * (1.f - wy) + v01 * wx * (1.f - wy)
          + v10 * (1.f - wx) * wy + v11 * wx * wy;
  flat[(size_t)rest * KP1 + kk * DM + c] = v;
}

__global__ __launch_bounds__(256)
void k_mean(const float* __restrict__ pv, float* __restrict__ kvpre) {
  int m = blockIdx.x, d = threadIdx.x;
  float s = 0.f;
  #pragma unroll
  for (int p = 0; p < NP; ++p) s += pv[(size_t)(m * NP + p) * DM + d];
  kvpre[m * DM + d] = s * (1.f / NP);
}

__global__ __launch_bounds__(256)
void k_kvT(const float* __restrict__ kv, float* __restrict__ kvT) {
  int m = blockIdx.x;
  int b = (m >= NQ) ? 1 : 0;
  int k = m - b * NQ;
  int d = threadIdx.x;
  kvT[((size_t)b * DM + d) * NQ + k] = kv[(size_t)m * DM + d];
}

__global__ __launch_bounds__(512)
void k_softmax(float* __restrict__ S) {
  int m = blockIdx.x;
  int b = (m >= NQ) ? 1 : 0;
  float* row = S + (size_t)b * NQ * NQ + (size_t)(m - b * NQ) * NQ;
  int t = threadIdx.x;
  __shared__ float red[512];
  float v = (t < NQ) ? row[t] * 0.0625f : -1e30f;
  red[t] = v; __syncthreads();
  for (int s = 256; s > 0; s >>= 1) { if (t < s) red[t] = fmaxf(red[t], red[t + s]); __syncthreads(); }
  float mx = red[0]; __syncthreads();
  float e = (t < NQ) ? expf(v - mx) : 0.f;
  red[t] = e; __syncthreads();
  for (int s = 256; s > 0; s >>= 1) { if (t < s) red[t] += red[t + s]; __syncthreads(); }
  float inv = 1.f / red[0];
  if (t < NQ) row[t] = e * inv;
}

__global__ __launch_bounds__(128)
void k_box(const float* __restrict__ hb, const float* __restrict__ w_b2,
           const float* __restrict__ b_b2, float* __restrict__ boxes) {
  int m = blockIdx.x;
  int wj = threadIdx.x >> 5, lane = threadIdx.x & 31;
  float s = 0.f;
  for (int d = lane; d < DM; d += 32) s += hb[m * DM + d] * w_b2[wj * DM + d];
  #pragma unroll
  for (int off = 16; off > 0; off >>= 1) s += __shfl_down_sync(0xffffffffu, s, off);
  if (lane == 0) {
    float delta = 1.f / (1.f + expf(-(s + b_b2[wj])));
    float nb = boxes[m * 4 + wj] + 0.1f * tanhf(delta - 0.5f);
    boxes[m * 4 + wj] = fminf(fmaxf(nb, 0.f), 1.f);
  }
}

__global__ __launch_bounds__(256)
void k_logits(const float* __restrict__ queries, const float* __restrict__ w_cls,
              const float* __restrict__ b_cls, float* __restrict__ out) {
  int m = blockIdx.x, t = threadIdx.x;
  __shared__ float red[256];
  red[t] = queries[m * DM + t] * w_cls[t];
  __syncthreads();
  for (int s = 128; s > 0; s >>= 1) { if (t < s) red[t] += red[t + s]; __syncthreads(); }
  if (t == 0) out[m] = red[0] + b_cls[0];
}

__global__ __launch_bounds__(256)
void k_copyboxes(const float* __restrict__ boxes, float* __restrict__ out) {
  int i = blockIdx.x * 256 + threadIdx.x;
  if (i < MQ * 4) out[MQ + i] = boxes[i];
}

// ---------------------------------------------------------------------------
static inline dim3 ggrid(int M, int N, int Z = 1) {
  return dim3((N + 63) / 64, (M + 127) / 128, Z);
}
#define GSMEM 98304

extern "C" void kernel_launch(void* const* d_in, const int* in_sizes, int n_in,
                              void* d_out, int out_size) {
  const float* feat   = (const float*)d_in[0];
  const float* boxes0 = (const float*)d_in[1];
  const float* w_tf   = (const float*)d_in[2];
  const float* b_tf   = (const float*)d_in[3];
  const float* w_in   = (const float*)d_in[4];
  const float* b_in   = (const float*)d_in[5];
  const float* w_lat  = (const float*)d_in[6];
  const float* b_lat  = (const float*)d_in[7];
  const float* w_sm   = (const float*)d_in[8];
  const float* b_sm   = (const float*)d_in[9];
  const float* q_embed= (const float*)d_in[10];
  const float* q_pos  = (const float*)d_in[11];
  const float* Wq     = (const float*)d_in[12];
  const float* bq     = (const float*)d_in[13];
  const float* Wo     = (const float*)d_in[14];
  const float* bo     = (const float*)d_in[15];
  const float* Wp1    = (const float*)d_in[16];
  const float* bp1    = (const float*)d_in[17];
  const float* Wp2    = (const float*)d_in[18];
  const float* bp2    = (const float*)d_in[19];
  const float* w_r1   = (const float*)d_in[20];
  const float* b_r1   = (const float*)d_in[21];
  const float* w_r2   = (const float*)d_in[22];
  const float* b_r2   = (const float*)d_in[23];
  const float* w_b1   = (const float*)d_in[24];
  const float* b_b1   = (const float*)d_in[25];
  const float* w_b2   = (const float*)d_in[26];
  const float* b_b2   = (const float*)d_in[27];
  const float* w_cls  = (const float*)d_in[28];
  const float* b_cls  = (const float*)d_in[29];
  float* out = (float*)d_out;

  static bool attr_done = false;
  if (!attr_done) {
    cudaFuncSetAttribute(gemm_tf32<0,0>, cudaFuncAttributeMaxDynamicSharedMemorySize, GSMEM);
    cudaFuncSetAttribute(gemm_tf32<1,0>, cudaFuncAttributeMaxDynamicSharedMemorySize, GSMEM);
    cudaFuncSetAttribute(gemm_tf32<2,0>, cudaFuncAttributeMaxDynamicSharedMemorySize, GSMEM);
    cudaFuncSetAttribute(gemm_tf32<0,1>, cudaFuncAttributeMaxDynamicSharedMemorySize, GSMEM);
    attr_done = true;
  }

  float* base = nullptr;
  cudaGetSymbolAddress((void**)&base, g_buf);
  float* p_wcomb = base + O_WCOMB;
  float* p_bcomb = base + O_BCOMB;
  float* p_py    = base + O_PY;
  float* p_px    = base + O_PX;
  float* p_wsmp  = base + O_WSMP;
  float* p_x     = base + O_X;
  float* p_lat   = base + O_LAT;
  float* p_f0    = base + O_F0;
  float* p_q     = base + O_Q;
  float* p_h1    = base + O_H1;
  float* p_ref   = base + O_REF;
  float* p_flat  = base + O_FLAT;
  float* p_pv    = base + O_PV;
  float* p_kvp   = base + O_KVP;
  float* p_kv    = base + O_KV;
  float* p_qp    = base + O_QP;
  float* p_kvT   = base + O_KVT;
  float* p_S     = base + O_S;
  float* p_ao    = base + O_AO;
  float* p_hb    = base + O_HB;
  float* p_box   = base + O_BOX;

  // ---- stem (conv3d + mean_T + in-proj fused) + pos + weight permute ----
  k_wcomb<<<(256 * 512 + 255) / 256, 256>>>(w_tf, w_in, b_tf, b_in, p_wcomb, p_bcomb);
  k_pos<<<(2 * 64 * 128 + 255) / 256, 256>>>(p_py, p_px);
  k_wsmperm<<<(DM * KP1 + 255) / 256, 256>>>(w_sm, p_wsmp);
  k_stem<<<dim3(4, 64), 256>>>(feat, p_wcomb, p_bcomb, p_py, p_px, p_x);

  // ---- scale-1 feature only (scales 2,4 dead in reference) ----
  gemm_tf32<0,0><<<ggrid(MROWS, DM), 256, GSMEM>>>(p_x, w_lat, b_lat, nullptr, p_lat, MROWS, DM, DM, 0, 0, 0);
  // smooth 3x3 conv: im2col fused into A-loader, permuted weights
  gemm_tf32<0,1><<<ggrid(MROWS, DM), 256, GSMEM>>>(p_lat, p_wsmp, b_sm, nullptr, p_f0, MROWS, DM, KP1, 0, 0, 0);

  // ---- decoder init ----
  k_qinit<<<MQ, 256>>>(q_embed, q_pos, boxes0, p_q, p_box);

  for (int l = 0; l < NLAY; ++l) {
    const float* Wq_l  = Wq  + (size_t)l * DM * DM;
    const float* bq_l  = bq  + (size_t)l * DM;
    const float* Wo_l  = Wo  + (size_t)l * DM * DM;
    const float* bo_l  = bo  + (size_t)l * DM;
    const float* Wp1_l = Wp1 + (size_t)l * DM * KP1;
    const float* bp1_l = bp1 + (size_t)l * DM;
    const float* Wp2_l = Wp2 + (size_t)l * DM * DM;
    const float* bp2_l = bp2 + (size_t)l * DM;

    gemm_tf32<1,0><<<ggrid(MQ, DM), 256, GSMEM>>>(p_q, w_r1, b_r1, nullptr, p_h1, MQ, DM, DM, 0, 0, 0);
    k_refpts<<<MQ, 256>>>(p_h1, p_box, w_r2, b_r2, p_ref);

    k_sample<<<MQ * NP * 9, 256>>>(p_f0, p_ref, p_flat);

    gemm_tf32<1,0><<<ggrid(MS, DM), 256, GSMEM>>>(p_flat, Wp1_l, bp1_l, nullptr, p_pv, MS, DM, KP1, 0, 0, 0);
    k_mean<<<MQ, 256>>>(p_pv, p_kvp);
    gemm_tf32<0,0><<<ggrid(MQ, DM), 256, GSMEM>>>(p_kvp, Wp2_l, bp2_l, nullptr, p_kv, MQ, DM, DM, 0, 0, 0);

    gemm_tf32<0,0><<<ggrid(MQ, DM), 256, GSMEM>>>(p_q, Wq_l, bq_l, nullptr, p_qp, MQ, DM, DM, 0, 0, 0);
    k_kvT<<<MQ, 256>>>(p_kv, p_kvT);
    gemm_tf32<0,0><<<ggrid(NQ, NQ, BATCH), 256, GSMEM>>>(p_qp, p_kv, nullptr, nullptr, p_S,
                                                         NQ, NQ, DM,
                                                         (long long)NQ * DM, (long long)NQ * DM,
                                                         (long long)NQ * NQ);
    k_softmax<<<MQ, 512>>>(p_S);
    gemm_tf32<0,0><<<ggrid(NQ, DM, BATCH), 256, GSMEM>>>(p_S, p_kvT, nullptr, nullptr, p_ao,
                                                         NQ, DM, NQ,
                                                         (long long)NQ * NQ, (long long)DM * NQ,
                                                         (long long)NQ * DM);
    gemm_tf32<2,0><<<ggrid(MQ, DM), 256, GSMEM>>>(p_ao, Wo_l, bo_l, p_q, p_q, MQ, DM, DM, 0, 0, 0);

    gemm_tf32<1,0><<<ggrid(MQ, DM), 256, GSMEM>>>(p_q, w_b1, b_b1, nullptr, p_hb, MQ, DM, DM, 0, 0, 0);
    k_box<<<MQ, 128>>>(p_hb, w_b2, b_b2, p_box);
  }

  k_logits<<<MQ, 256>>>(p_q, w_cls, b_cls, out);
  k_copyboxes<<<(MQ * 4 + 255) / 256, 256>>>(p_box, out);
}

// round 7
// speedup vs baseline: 1.9885x; 1.4504x over previous
#include <cuda_runtime.h>
#include <cuda_bf16.h>
#include <math.h>
#include <stdint.h>

// ---------------------------------------------------------------------------
// Problem constants
// ---------------------------------------------------------------------------
#define HH 64
#define WW 64
#define HWSZ 4096
#define CIN 128
#define TT 4
#define DM 256
#define NQ 300
#define NP 8
#define NLAY 6
#define BATCH 2
#define MROWS (BATCH*HWSZ)      // 8192 spatial rows
#define MQ (BATCH*NQ)           // 600 query rows
#define MS (MQ*NP)              // 4800 sample rows
#define KP1 2304                // 3*3*256

// ---------------------------------------------------------------------------
// Scratch
// ---------------------------------------------------------------------------
constexpr size_t O_WCOMB = 0;                        // 256*512
constexpr size_t O_BCOMB = O_WCOMB + 256*512;        // 256
constexpr size_t O_PY    = O_BCOMB + 256;            // 64*128
constexpr size_t O_PX    = O_PY + 64*128;            // 64*128
constexpr size_t O_WSMP  = O_PX + 64*128;            // 256*2304 permuted w_sm
constexpr size_t O_X     = O_WSMP + (size_t)DM*KP1;  // 8192*256
constexpr size_t O_LAT   = O_X + (size_t)MROWS*DM;   // 8192*256
constexpr size_t O_F0    = O_LAT + (size_t)MROWS*DM; // 8192*256
constexpr size_t O_Q     = O_F0 + (size_t)MROWS*DM;  // 600*256
constexpr size_t O_H1    = O_Q + MQ*DM;
constexpr size_t O_REF   = O_H1 + MQ*DM;             // 600*8*2
constexpr size_t O_FLAT  = O_REF + MQ*NP*2;          // 4800*2304
constexpr size_t O_PV    = O_FLAT + (size_t)MS*KP1;  // 4800*256
constexpr size_t O_KVP   = O_PV + (size_t)MS*DM;
constexpr size_t O_KV    = O_KVP + MQ*DM;
constexpr size_t O_QP    = O_KV + MQ*DM;
constexpr size_t O_KVT   = O_QP + MQ*DM;             // 2*256*300
constexpr size_t O_S     = O_KVT + MQ*DM;            // 2*300*300
constexpr size_t O_AO    = O_S + BATCH*NQ*NQ;
constexpr size_t O_HB    = O_AO + MQ*DM;
constexpr size_t O_BOX   = O_HB + MQ*DM;             // 600*4
constexpr size_t G_TOTAL = O_BOX + MQ*4;

__device__ float g_buf[G_TOTAL];

// ---------------------------------------------------------------------------
// BF16 split helpers: x = hi + lo with |lo| <~ 2^-9 |x|, residual ~2^-17.
// ---------------------------------------------------------------------------
__device__ __forceinline__ void split_bf16(float x, float& hf, float& lf) {
  __nv_bfloat16 h = __float2bfloat16(x);
  hf = __bfloat162float(h);
  lf = x - hf;                      // exact in fp32
}
__device__ __forceinline__ uint32_t pack_bf16(float lo_elem, float hi_elem) {
  __nv_bfloat162 t = __floats2bfloat162_rn(lo_elem, hi_elem); // .x=low half
  return *reinterpret_cast<uint32_t*>(&t);
}
__device__ __forceinline__ void mma_bf16(float* c, const uint32_t* a, const uint32_t* b) {
  asm volatile(
    "mma.sync.aligned.m16n8k16.row.col.f32.bf16.bf16.f32 "
    "{%0,%1,%2,%3},{%4,%5,%6,%7},{%8,%9},{%0,%1,%2,%3};"
    : "+f"(c[0]), "+f"(c[1]), "+f"(c[2]), "+f"(c[3])
    : "r"(a[0]), "r"(a[1]), "r"(a[2]), "r"(a[3]), "r"(b[0]), "r"(b[1]));
}

// ---------------------------------------------------------------------------
// 3xBF16 GEMM (Karatsuba hi/lo, fp32-grade accuracy ~1e-5).
// Block 128x64, 8 warps of 32x32, BK=32 (= 2 k-chunks of 16), double-buffered
// 48KB dynamic smem, fragment-layout + XOR swizzle. m16n8k16 MMA.
// GATHER=1: A gathered as im2col ([ky][kx][c] K-order) of (b,64,64,256)
//           channel-last map; pair with [o][ky][kx][c]-permuted weights.
// EPI: 0=+bias, 1=+bias+relu, 2=+bias+res. Batched via blockIdx.z strides.
// ---------------------------------------------------------------------------
template<int EPI, int GATHER>
__global__ __launch_bounds__(256, 2)
void gemm_b16(const float* __restrict__ A, const float* __restrict__ Bw,
              const float* __restrict__ bias, const float* __restrict__ res,
              float* __restrict__ C, int M, int N, int K,
              long long sA, long long sB, long long sC) {
  const int BM = 128, BN = 64, BK = 32;
  extern __shared__ uint32_t smem[];
  uint32_t* SAb = smem;            // 2 x 4096 words (16KB each)
  uint32_t* SBb = smem + 8192;     // 2 x 2048 words (8KB each)

  A  += blockIdx.z * sA;
  Bw += blockIdx.z * sB;
  C  += blockIdx.z * sC;

  int tid = threadIdx.x;
  int bm = blockIdx.y * BM, bn = blockIdx.x * BN;
  int lane = tid & 31, warp = tid >> 5;
  int wm = (warp >> 1) * 32, wn = (warp & 1) * 32;
  int gid = lane >> 2, tig = lane & 3;
  int xr = (lane >> 2) & 7;

  float acc[2][4][4] = {};
  int Kpad = (K + BK - 1) / BK * BK;

  int am4[4], ak4[4], bn2[2], bk2[2];
  #pragma unroll
  for (int l = 0; l < 4; ++l) {
    int li = tid + l * 256;
    am4[l] = li >> 3;          // 0..127
    ak4[l] = (li & 7) * 4;     // 0..28 step 4
  }
  #pragma unroll
  for (int l = 0; l < 2; ++l) {
    int li = tid + l * 256;
    bn2[l] = li >> 3;          // 0..63
    bk2[l] = (li & 7) * 4;
  }

  float4 pa[4], pb[2];

  auto loadA = [&](int k0, int l) -> float4 {
    float4 v = make_float4(0.f, 0.f, 0.f, 0.f);
    int gm = bm + am4[l], gk = k0 + ak4[l];
    if (GATHER) {
      if (gm < M && gk < K) {
        int ky = gk / 768, rem = gk - ky * 768;
        int kx = rem >> 8, c = rem & 255;
        int b = gm >> 12, hw = gm & 4095, h = hw >> 6, w = hw & 63;
        int hh = h + ky - 1, ww = w + kx - 1;
        if (hh >= 0 && hh < 64 && ww >= 0 && ww < 64)
          v = *reinterpret_cast<const float4*>(A + ((size_t)(b << 12) + (hh << 6) + ww) * 256 + c);
      }
    } else {
      if (gm < M) {
        if (gk + 3 < K) v = *reinterpret_cast<const float4*>(A + (size_t)gm * K + gk);
        else {
          float t[4] = {0.f, 0.f, 0.f, 0.f};
          #pragma unroll
          for (int e = 0; e < 4; ++e) if (gk + e < K) t[e] = A[(size_t)gm * K + gk + e];
          v = make_float4(t[0], t[1], t[2], t[3]);
        }
      }
    }
    return v;
  };
  auto loadB = [&](int k0, int l) -> float4 {
    float4 v = make_float4(0.f, 0.f, 0.f, 0.f);
    int gn = bn + bn2[l], gk = k0 + bk2[l];
    if (gn < N) {
      if (gk + 3 < K) v = *reinterpret_cast<const float4*>(Bw + (size_t)gn * K + gk);
      else {
        float t[4] = {0.f, 0.f, 0.f, 0.f};
        #pragma unroll
        for (int e = 0; e < 4; ++e) if (gk + e < K) t[e] = Bw[(size_t)gn * K + gk + e];
        v = make_float4(t[0], t[1], t[2], t[3]);
      }
    }
    return v;
  };
  auto prefetch = [&](int k0) {
    #pragma unroll
    for (int l = 0; l < 4; ++l) pa[l] = loadA(k0, l);
    #pragma unroll
    for (int l = 0; l < 2; ++l) pb[l] = loadB(k0, l);
  };

  auto storeTiles = [&](int buf) {
    uint32_t* SA = SAb + buf * 4096;
    uint32_t* SB = SBb + buf * 2048;
    #pragma unroll
    for (int l = 0; l < 4; ++l) {
      float v[4] = {pa[l].x, pa[l].y, pa[l].z, pa[l].w};
      int tm = am4[l] >> 4, rr = am4[l] & 15;
      int tk = ak4[l] >> 4, k16b = ak4[l] & 15;    // 0,4,8,12
      #pragma unroll
      for (int e = 0; e < 2; ++e) {
        int k16p = k16b + 2 * e;
        int lw = (rr & 7) * 4 + ((k16p >> 1) & 3);
        int reg = (rr >> 3) | ((k16p >> 3) << 1);
        float h0, l0, h1, l1;
        split_bf16(v[2 * e], h0, l0);
        split_bf16(v[2 * e + 1], h1, l1);
        int s0 = (((tm * 2 + tk) * 32 + lw) * 2) ^ ((lw >> 2) & 7);
        SA[s0 * 4 + reg]       = pack_bf16(h0, h1);
        SA[(s0 ^ 1) * 4 + reg] = pack_bf16(l0, l1);
      }
    }
    #pragma unroll
    for (int l = 0; l < 2; ++l) {
      float v[4] = {pb[l].x, pb[l].y, pb[l].z, pb[l].w};
      int ntile = bn2[l] >> 3, gidn = bn2[l] & 7;
      int np = ntile >> 1, nodd = ntile & 1;
      int tk = bk2[l] >> 4, k16b = bk2[l] & 15;
      #pragma unroll
      for (int e = 0; e < 2; ++e) {
        int k16p = k16b + 2 * e;
        int lw = gidn * 4 + ((k16p >> 1) & 3);
        int reg = k16p >> 3;                      // b0/b1
        int word = nodd * 2 + reg;
        float h0, l0, h1, l1;
        split_bf16(v[2 * e], h0, l0);
        split_bf16(v[2 * e + 1], h1, l1);
        int s0 = (((np * 2 + tk) * 32 + lw) * 2) ^ ((lw >> 2) & 7);
        SB[s0 * 4 + word]       = pack_bf16(h0, h1);
        SB[(s0 ^ 1) * 4 + word] = pack_bf16(l0, l1);
      }
    }
  };

  prefetch(0);
  storeTiles(0);
  if (BK < Kpad) prefetch(BK);
  __syncthreads();

  int cur = 0;
  for (int k0 = 0; k0 < Kpad; k0 += BK) {
    if (k0 + BK < Kpad) {
      storeTiles(cur ^ 1);
      if (k0 + 2 * BK < Kpad) prefetch(k0 + 2 * BK);
    }
    const uint32_t* SA = SAb + cur * 4096;
    const uint32_t* SB = SBb + cur * 2048;
    #pragma unroll
    for (int tk = 0; tk < 2; ++tk) {
      uint32_t Ahf[2][4], Alf[2][4];
      #pragma unroll
      for (int i = 0; i < 2; ++i) {
        int tm = (wm >> 4) + i;
        int s0 = (((tm * 2 + tk) * 32 + lane) * 2) ^ xr;
        *reinterpret_cast<uint4*>(Ahf[i]) = *reinterpret_cast<const uint4*>(&SA[s0 * 4]);
        *reinterpret_cast<uint4*>(Alf[i]) = *reinterpret_cast<const uint4*>(&SA[(s0 ^ 1) * 4]);
      }
      uint32_t Bhf[2][4], Blf[2][4];
      #pragma unroll
      for (int jp = 0; jp < 2; ++jp) {
        int np = (wn >> 4) + jp;
        int s0 = (((np * 2 + tk) * 32 + lane) * 2) ^ xr;
        *reinterpret_cast<uint4*>(Bhf[jp]) = *reinterpret_cast<const uint4*>(&SB[s0 * 4]);
        *reinterpret_cast<uint4*>(Blf[jp]) = *reinterpret_cast<const uint4*>(&SB[(s0 ^ 1) * 4]);
      }
      #pragma unroll
      for (int i = 0; i < 2; ++i)
        #pragma unroll
        for (int jp = 0; jp < 2; ++jp)
          #pragma unroll
          for (int nodd = 0; nodd < 2; ++nodd) {
            int j = jp * 2 + nodd;
            uint32_t bh[2] = {Bhf[jp][nodd * 2], Bhf[jp][nodd * 2 + 1]};
            uint32_t bl[2] = {Blf[jp][nodd * 2], Blf[jp][nodd * 2 + 1]};
            mma_bf16(acc[i][j], Ahf[i], bh);
            mma_bf16(acc[i][j], Ahf[i], bl);
            mma_bf16(acc[i][j], Alf[i], bh);
          }
    }
    __syncthreads();
    cur ^= 1;
  }

  #pragma unroll
  for (int i = 0; i < 2; ++i) {
    #pragma unroll
    for (int j = 0; j < 4; ++j) {
      int c0 = bn + wn + 8 * j + 2 * tig;
      #pragma unroll
      for (int half = 0; half < 2; ++half) {
        int gm = bm + wm + 16 * i + gid + 8 * half;
        if (gm >= M) continue;
        #pragma unroll
        for (int e = 0; e < 2; ++e) {
          int gn = c0 + e;
          if (gn >= N) continue;
          float v = acc[i][j][half * 2 + e] + (bias ? bias[gn] : 0.f);
          if (EPI == 1) v = fmaxf(v, 0.f);
          if (EPI == 2) v += res[(size_t)gm * N + gn];
          C[(size_t)gm * N + gn] = v;
        }
      }
    }
  }
}

// ---------------------------------------------------------------------------
// Permute w_sm [o][c][ky][kx] -> [o][ky][kx][c]  (match GATHER K-order)
// ---------------------------------------------------------------------------
__global__ __launch_bounds__(256)
void k_wsmperm(const float* __restrict__ w_sm, float* __restrict__ out) {
  int idx = blockIdx.x * 256 + threadIdx.x;
  if (idx >= DM * KP1) return;
  int o = idx / KP1, r = idx - o * KP1;
  int ky = r / 768, rem = r - ky * 768;
  int kx = rem >> 8, c = rem & 255;
  out[idx] = w_sm[(size_t)o * KP1 + c * 9 + ky * 3 + kx];
}

// ---------------------------------------------------------------------------
// Stem weight combine
// ---------------------------------------------------------------------------
__global__ __launch_bounds__(256)
void k_wcomb(const float* __restrict__ w_tf, const float* __restrict__ w_in,
             const float* __restrict__ b_tf, const float* __restrict__ b_in,
             float* __restrict__ wcomb, float* __restrict__ bcomb) {
  int idx = blockIdx.x * 256 + threadIdx.x;
  if (idx < 256 * 512) {
    int dm = idx >> 9, k = idx & 511, i = k >> 2, t = k & 3;
    float s = 0.f;
    for (int c = 0; c < CIN; ++c) {
      const float* wt = w_tf + (c * CIN + i) * 3;
      float we = wt[1];
      if (t != 3) we += wt[0];
      if (t != 0) we += wt[2];
      s += w_in[dm * CIN + c] * we;
    }
    wcomb[idx] = 0.25f * s;
  }
  if (idx < 256) {
    float s = b_in[idx];
    for (int c = 0; c < CIN; ++c) s += w_in[idx * CIN + c] * b_tf[c];
    bcomb[idx] = s;
  }
}

__global__ __launch_bounds__(256)
void k_pos(float* __restrict__ py, float* __restrict__ px) {
  int idx = blockIdx.x * 256 + threadIdx.x;
  if (idx >= 2 * 64 * 128) return;
  int half = idx / (64 * 128);
  int r = idx - half * (64 * 128);
  int hw = r >> 7, c = r & 127;
  float dim_t = powf(10000.f, 2.f * (float)(c >> 2) / 64.f);
  float v = (float)(hw + 1) / (64.f + 1e-6f) * 2.f * 3.14159265358979323846f;
  float a = v / dim_t;
  float o = (c & 1) ? cosf(a) : sinf(a);
  if (half) px[r] = o; else py[r] = o;
}

// ---------------------------------------------------------------------------
// Stem GEMM (fp32, gathered A)
// ---------------------------------------------------------------------------
__global__ __launch_bounds__(256)
void k_stem(const float* __restrict__ feat, const float* __restrict__ wcomb,
            const float* __restrict__ bcomb, const float* __restrict__ py,
            const float* __restrict__ px, float* __restrict__ C) {
  const int BM = 128, BN = 64, BK = 16, K = 512, N = 256;
  __shared__ float As[BK][BM + 4];
  __shared__ float Bs[BK][BN + 4];
  int bm = blockIdx.y * BM, bn = blockIdx.x * BN;
  int tid = threadIdx.x;
  int tx = tid & 15, ty = tid >> 4;
  float acc[8][4] = {};
  for (int k0 = 0; k0 < K; k0 += BK) {
    #pragma unroll
    for (int l = 0; l < 8; ++l) {
      int e = tid + l * 256;
      int k = e >> 7, mm = e & 127;
      int gm = bm + mm, gk = k0 + k;
      int b = gm >> 12, hw = gm & 4095;
      int i = gk >> 2, t = gk & 3;
      As[k][mm] = feat[(size_t)(((b << 2) + t) * CIN + i) * HWSZ + hw];
    }
    {
      int m = tid >> 2, kq = (tid & 3) * 4;
      float4 v = *reinterpret_cast<const float4*>(wcomb + (size_t)(bn + m) * K + k0 + kq);
      Bs[kq + 0][m] = v.x; Bs[kq + 1][m] = v.y;
      Bs[kq + 2][m] = v.z; Bs[kq + 3][m] = v.w;
    }
    __syncthreads();
    #pragma unroll
    for (int kk = 0; kk < BK; ++kk) {
      float4 a0 = *reinterpret_cast<const float4*>(&As[kk][ty * 8]);
      float4 a1 = *reinterpret_cast<const float4*>(&As[kk][ty * 8 + 4]);
      float4 b0 = *reinterpret_cast<const float4*>(&Bs[kk][tx * 4]);
      float a[8] = {a0.x, a0.y, a0.z, a0.w, a1.x, a1.y, a1.z, a1.w};
      float b[4] = {b0.x, b0.y, b0.z, b0.w};
      #pragma unroll
      for (int i = 0; i < 8; ++i)
        #pragma unroll
        for (int j = 0; j < 4; ++j) acc[i][j] += a[i] * b[j];
    }
    __syncthreads();
  }
  #pragma unroll
  for (int i = 0; i < 8; ++i) {
    int gm = bm + ty * 8 + i;
    int hw = gm & 4095;
    int h = hw >> 6, w = hw & 63;
    #pragma unroll
    for (int j = 0; j < 4; ++j) {
      int gn = bn + tx * 4 + j;
      float pos = (gn < 128) ? py[h * 128 + gn] : px[w * 128 + gn - 128];
      C[(size_t)gm * N + gn] = acc[i][j] + bcomb[gn] + pos;
    }
  }
}

__global__ __launch_bounds__(256)
void k_qinit(const float* __restrict__ q_embed, const float* __restrict__ q_pos,
             const float* __restrict__ boxes0, float* __restrict__ queries,
             float* __restrict__ boxes) {
  int m = blockIdx.x;
  int q = m % NQ;
  int d = threadIdx.x;
  queries[m * DM + d] = q_embed[q * DM + d] + q_pos[q * DM + d];
  if (d < 4) boxes[m * 4 + d] = boxes0[m * 4 + d];
}

__global__ __launch_bounds__(256)
void k_refpts(const float* __restrict__ h1, const float* __restrict__ boxes,
              const float* __restrict__ w_r2, const float* __restrict__ b_r2,
              float* __restrict__ ref) {
  int m = blockIdx.x;
  int g = threadIdx.x >> 4;
  int lane16 = threadIdx.x & 15;
  float s = 0.f;
  for (int d = lane16; d < DM; d += 16)
    s += h1[m * DM + d] * w_r2[g * DM + d];
  #pragma unroll
  for (int off = 8; off > 0; off >>= 1)
    s += __shfl_down_sync(0xffffffffu, s, off, 16);
  __shared__ float ro_s[16];
  if (lane16 == 0) ro_s[g] = tanhf(s + b_r2[g]) * 0.5f;
  __syncthreads();
  if (threadIdx.x < 16) {
    int p = threadIdx.x >> 1, j = threadIdx.x & 1;
    float v = boxes[m * 4 + j] + ro_s[p * 2 + j];
    ref[(m * NP + p) * 2 + j] = fminf(fmaxf(v, 0.f), 1.f);
  }
}

__global__ __launch_bounds__(256)
void k_sample(const float* __restrict__ f0, const float* __restrict__ ref,
              float* __restrict__ flat) {
  int blk = blockIdx.x;
  int kk = blk % 9;
  int rest = blk / 9;
  int p = rest & 7, m = rest >> 3;
  int b = (m >= NQ) ? 1 : 0;
  float rx = ref[(m * NP + p) * 2 + 0];
  float ry = ref[(m * NP + p) * 2 + 1];
  float oy = (float)(kk / 3 - 1), ox = (float)(kk % 3 - 1);
  float x = fminf(fmaxf((rx + ox * (1.f / 64.f)) * 63.f, 0.f), 63.f);
  float y = fminf(fmaxf((ry + oy * (1.f / 64.f)) * 63.f, 0.f), 63.f);
  float x0 = floorf(x), y0 = floorf(y);
  float wx = x - x0, wy = y - y0;
  int x0i = (int)x0, y0i = (int)y0;
  int x1i = min(x0i + 1, 63), y1i = min(y0i + 1, 63);
  int c = threadIdx.x;
  const float* f = f0 + (size_t)b * HWSZ * DM;
  float v00 = f[((y0i << 6) + x0i) * DM + c];
  float v01 = f[((y0i << 6) + x1i) * DM + c];
  float v10 = f[((y1i << 6) + x0i) * DM + c];
  float v11 = f[((y1i << 6) + x1i) * DM + c];
  float v = v00 * (1.f - wx) * (1.f - wy) + v01 * wx * (1.f - wy)
          + v10 * (1.f - wx) * wy + v11 * wx * wy;
  flat[(size_t)rest * KP1 + kk * DM + c] = v;
}

__global__ __launch_bounds__(256)
void k_mean(const float* __restrict__ pv, float* __restrict__ kvpre) {
  int m = blockIdx.x, d = threadIdx.x;
  float s = 0.f;
  #pragma unroll
  for (int p = 0; p < NP; ++p) s += pv[(size_t)(m * NP + p) * DM + d];
  kvpre[m * DM + d] = s * (1.f / NP);
}

__global__ __launch_bounds__(256)
void k_kvT(const float* __restrict__ kv, float* __restrict__ kvT) {
  int m = blockIdx.x;
  int b = (m >= NQ) ? 1 : 0;
  int k = m - b * NQ;
  int d = threadIdx.x;
  kvT[((size_t)b * DM + d) * NQ + k] = kv[(size_t)m * DM + d];
}

__global__ __launch_bounds__(512)
void k_softmax(float* __restrict__ S) {
  int m = blockIdx.x;
  int b = (m >= NQ) ? 1 : 0;
  float* row = S + (size_t)b * NQ * NQ + (size_t)(m - b * NQ) * NQ;
  int t = threadIdx.x;
  __shared__ float red[512];
  float v = (t < NQ) ? row[t] * 0.0625f : -1e30f;
  red[t] = v; __syncthreads();
  for (int s = 256; s > 0; s >>= 1) { if (t < s) red[t] = fmaxf(red[t], red[t + s]); __syncthreads(); }
  float mx = red[0]; __syncthreads();
  float e = (t < NQ) ? expf(v - mx) : 0.f;
  red[t] = e; __syncthreads();
  for (int s = 256; s > 0; s >>= 1) { if (t < s) red[t] += red[t + s]; __syncthreads(); }
  float inv = 1.f / red[0];
  if (t < NQ) row[t] = e * inv;
}

__global__ __launch_bounds__(128)
void k_box(const float* __restrict__ hb, const float* __restrict__ w_b2,
           const float* __restrict__ b_b2, float* __restrict__ boxes) {
  int m = blockIdx.x;
  int wj = threadIdx.x >> 5, lane = threadIdx.x & 31;
  float s = 0.f;
  for (int d = lane; d < DM; d += 32) s += hb[m * DM + d] * w_b2[wj * DM + d];
  #pragma unroll
  for (int off = 16; off > 0; off >>= 1) s += __shfl_down_sync(0xffffffffu, s, off);
  if (lane == 0) {
    float delta = 1.f / (1.f + expf(-(s + b_b2[wj])));
    float nb = boxes[m * 4 + wj] + 0.1f * tanhf(delta - 0.5f);
    boxes[m * 4 + wj] = fminf(fmaxf(nb, 0.f), 1.f);
  }
}

__global__ __launch_bounds__(256)
void k_logits(const float* __restrict__ queries, const float* __restrict__ w_cls,
              const float* __restrict__ b_cls, float* __restrict__ out) {
  int m = blockIdx.x, t = threadIdx.x;
  __shared__ float red[256];
  red[t] = queries[m * DM + t] * w_cls[t];
  __syncthreads();
  for (int s = 128; s > 0; s >>= 1) { if (t < s) red[t] += red[t + s]; __syncthreads(); }
  if (t == 0) out[m] = red[0] + b_cls[0];
}

__global__ __launch_bounds__(256)
void k_copyboxes(const float* __restrict__ boxes, float* __restrict__ out) {
  int i = blockIdx.x * 256 + threadIdx.x;
  if (i < MQ * 4) out[MQ + i] = boxes[i];
}

// ---------------------------------------------------------------------------
static inline dim3 ggrid(int M, int N, int Z = 1) {
  return dim3((N + 63) / 64, (M + 127) / 128, Z);
}
#define GSMEM 49152

extern "C" void kernel_launch(void* const* d_in, const int* in_sizes, int n_in,
                              void* d_out, int out_size) {
  const float* feat   = (const float*)d_in[0];
  const float* boxes0 = (const float*)d_in[1];
  const float* w_tf   = (const float*)d_in[2];
  const float* b_tf   = (const float*)d_in[3];
  const float* w_in   = (const float*)d_in[4];
  const float* b_in   = (const float*)d_in[5];
  const float* w_lat  = (const float*)d_in[6];
  const float* b_lat  = (const float*)d_in[7];
  const float* w_sm   = (const float*)d_in[8];
  const float* b_sm   = (const float*)d_in[9];
  const float* q_embed= (const float*)d_in[10];
  const float* q_pos  = (const float*)d_in[11];
  const float* Wq     = (const float*)d_in[12];
  const float* bq     = (const float*)d_in[13];
  const float* Wo     = (const float*)d_in[14];
  const float* bo     = (const float*)d_in[15];
  const float* Wp1    = (const float*)d_in[16];
  const float* bp1    = (const float*)d_in[17];
  const float* Wp2    = (const float*)d_in[18];
  const float* bp2    = (const float*)d_in[19];
  const float* w_r1   = (const float*)d_in[20];
  const float* b_r1   = (const float*)d_in[21];
  const float* w_r2   = (const float*)d_in[22];
  const float* b_r2   = (const float*)d_in[23];
  const float* w_b1   = (const float*)d_in[24];
  const float* b_b1   = (const float*)d_in[25];
  const float* w_b2   = (const float*)d_in[26];
  const float* b_b2   = (const float*)d_in[27];
  const float* w_cls  = (const float*)d_in[28];
  const float* b_cls  = (const float*)d_in[29];
  float* out = (float*)d_out;

  static bool attr_done = false;
  if (!attr_done) {
    cudaFuncSetAttribute(gemm_b16<0,0>, cudaFuncAttributeMaxDynamicSharedMemorySize, GSMEM);
    cudaFuncSetAttribute(gemm_b16<1,0>, cudaFuncAttributeMaxDynamicSharedMemorySize, GSMEM);
    cudaFuncSetAttribute(gemm_b16<2,0>, cudaFuncAttributeMaxDynamicSharedMemorySize, GSMEM);
    cudaFuncSetAttribute(gemm_b16<0,1>, cudaFuncAttributeMaxDynamicSharedMemorySize, GSMEM);
    attr_done = true;
  }

  float* base = nullptr;
  cudaGetSymbolAddress((void**)&base, g_buf);
  float* p_wcomb = base + O_WCOMB;
  float* p_bcomb = base + O_BCOMB;
  float* p_py    = base + O_PY;
  float* p_px    = base + O_PX;
  float* p_wsmp  = base + O_WSMP;
  float* p_x     = base + O_X;
  float* p_lat   = base + O_LAT;
  float* p_f0    = base + O_F0;
  float* p_q     = base + O_Q;
  float* p_h1    = base + O_H1;
  float* p_ref   = base + O_REF;
  float* p_flat  = base + O_FLAT;
  float* p_pv    = base + O_PV;
  float* p_kvp   = base + O_KVP;
  float* p_kv    = base + O_KV;
  float* p_qp    = base + O_QP;
  float* p_kvT   = base + O_KVT;
  float* p_S     = base + O_S;
  float* p_ao    = base + O_AO;
  float* p_hb    = base + O_HB;
  float* p_box   = base + O_BOX;

  // ---- stem (conv3d + mean_T + in-proj fused) + pos + weight permute ----
  k_wcomb<<<(256 * 512 + 255) / 256, 256>>>(w_tf, w_in, b_tf, b_in, p_wcomb, p_bcomb);
  k_pos<<<(2 * 64 * 128 + 255) / 256, 256>>>(p_py, p_px);
  k_wsmperm<<<(DM * KP1 + 255) / 256, 256>>>(w_sm, p_wsmp);
  k_stem<<<dim3(4, 64), 256>>>(feat, p_wcomb, p_bcomb, p_py, p_px, p_x);

  // ---- scale-1 feature only (scales 2,4 dead in reference) ----
  gemm_b16<0,0><<<ggrid(MROWS, DM), 256, GSMEM>>>(p_x, w_lat, b_lat, nullptr, p_lat, MROWS, DM, DM, 0, 0, 0);
  // smooth 3x3 conv: im2col fused into A-loader, permuted weights
  gemm_b16<0,1><<<ggrid(MROWS, DM), 256, GSMEM>>>(p_lat, p_wsmp, b_sm, nullptr, p_f0, MROWS, DM, KP1, 0, 0, 0);

  // ---- decoder init ----
  k_qinit<<<MQ, 256>>>(q_embed, q_pos, boxes0, p_q, p_box);

  for (int l = 0; l < NLAY; ++l) {
    const float* Wq_l  = Wq  + (size_t)l * DM * DM;
    const float* bq_l  = bq  + (size_t)l * DM;
    const float* Wo_l  = Wo  + (size_t)l * DM * DM;
    const float* bo_l  = bo  + (size_t)l * DM;
    const float* Wp1_l = Wp1 + (size_t)l * DM * KP1;
    const float* bp1_l = bp1 + (size_t)l * DM;
    const float* Wp2_l = Wp2 + (size_t)l * DM * DM;
    const float* bp2_l = bp2 + (size_t)l * DM;

    gemm_b16<1,0><<<ggrid(MQ, DM), 256, GSMEM>>>(p_q, w_r1, b_r1, nullptr, p_h1, MQ, DM, DM, 0, 0, 0);
    k_refpts<<<MQ, 256>>>(p_h1, p_box, w_r2, b_r2, p_ref);

    k_sample<<<MQ * NP * 9, 256>>>(p_f0, p_ref, p_flat);

    gemm_b16<1,0><<<ggrid(MS, DM), 256, GSMEM>>>(p_flat, Wp1_l, bp1_l, nullptr, p_pv, MS, DM, KP1, 0, 0, 0);
    k_mean<<<MQ, 256>>>(p_pv, p_kvp);
    gemm_b16<0,0><<<ggrid(MQ, DM), 256, GSMEM>>>(p_kvp, Wp2_l, bp2_l, nullptr, p_kv, MQ, DM, DM, 0, 0, 0);

    gemm_b16<0,0><<<ggrid(MQ, DM), 256, GSMEM>>>(p_q, Wq_l, bq_l, nullptr, p_qp, MQ, DM, DM, 0, 0, 0);
    k_kvT<<<MQ, 256>>>(p_kv, p_kvT);
    gemm_b16<0,0><<<ggrid(NQ, NQ, BATCH), 256, GSMEM>>>(p_qp, p_kv, nullptr, nullptr, p_S,
                                                        NQ, NQ, DM,
                                                        (long long)NQ * DM, (long long)NQ * DM,
                                                        (long long)NQ * NQ);
    k_softmax<<<MQ, 512>>>(p_S);
    gemm_b16<0,0><<<ggrid(NQ, DM, BATCH), 256, GSMEM>>>(p_S, p_kvT, nullptr, nullptr, p_ao,
                                                        NQ, DM, NQ,
                                                        (long long)NQ * NQ, (long long)DM * NQ,
                                                        (long long)NQ * DM);
    gemm_b16<2,0><<<ggrid(MQ, DM), 256, GSMEM>>>(p_ao, Wo_l, bo_l, p_q, p_q, MQ, DM, DM, 0, 0, 0);

    gemm_b16<1,0><<<ggrid(MQ, DM), 256, GSMEM>>>(p_q, w_b1, b_b1, nullptr, p_hb, MQ, DM, DM, 0, 0, 0);
    k_box<<<MQ, 128>>>(p_hb, w_b2, b_b2, p_box);
  }

  k_logits<<<MQ, 256>>>(p_q, w_cls, b_cls, out);
  k_copyboxes<<<(MQ * 4 + 255) / 256, 256>>>(p_box, out);
}